// round 14
// baseline (speedup 1.0000x reference)
#include <cuda_runtime.h>
#include <cuda_bf16.h>

#define B_ 8
#define T_ 12
#define N_ 1024
#define C_ 64
#define H_ 8
#define D_ 64
#define HD_ 512
#define BT_ 96
#define EPSV 1e-3f

__device__ __forceinline__ void split2(float x0, float x1, unsigned& hi, unsigned& lo) {
    __nv_bfloat16 h0 = __float2bfloat16(x0);
    __nv_bfloat16 h1 = __float2bfloat16(x1);
    __nv_bfloat16 l0 = __float2bfloat16(x0 - __bfloat162float(h0));
    __nv_bfloat16 l1 = __float2bfloat16(x1 - __bfloat162float(h1));
    hi = ((unsigned)__bfloat16_as_ushort(h1) << 16) | (unsigned)__bfloat16_as_ushort(h0);
    lo = ((unsigned)__bfloat16_as_ushort(l1) << 16) | (unsigned)__bfloat16_as_ushort(l0);
}
__device__ __forceinline__ unsigned long long splitpack(float x0, float x1) {
    unsigned h, l;
    split2(x0, x1, h, l);
    return (unsigned long long)h | ((unsigned long long)l << 32);
}
__device__ __forceinline__ void split1(float v, __nv_bfloat16& h, __nv_bfloat16& l) {
    h = __float2bfloat16(v);
    l = __float2bfloat16(v - __bfloat162float(h));
}
__device__ __forceinline__ void mma16816(float* c, unsigned a0, unsigned a1,
                                         unsigned a2, unsigned a3,
                                         unsigned b0, unsigned b1) {
    asm volatile(
        "mma.sync.aligned.m16n8k16.row.col.f32.bf16.bf16.f32 "
        "{%0,%1,%2,%3},{%4,%5,%6,%7},{%8,%9},{%0,%1,%2,%3};"
        : "+f"(c[0]), "+f"(c[1]), "+f"(c[2]), "+f"(c[3])
        : "r"(a0), "r"(a1), "r"(a2), "r"(a3), "r"(b0), "r"(b1));
}
__device__ __forceinline__ void ldsm_x4(unsigned& r0, unsigned& r1, unsigned& r2,
                                        unsigned& r3, unsigned addr) {
    asm volatile("ldmatrix.sync.aligned.m8n8.x4.shared.b16 {%0,%1,%2,%3}, [%4];"
                 : "=r"(r0), "=r"(r1), "=r"(r2), "=r"(r3) : "r"(addr));
}
__device__ __forceinline__ unsigned smem_u32addr(const void* p) {
    unsigned a;
    asm("{.reg .u64 t; cvta.to.shared.u64 t, %1; cvt.u32.u64 %0, t;}" : "=r"(a) : "l"(p));
    return a;
}
__device__ __forceinline__ void cpasync16(unsigned s, const void* g) {
    asm volatile("cp.async.cg.shared.global [%0],[%1],16;" :: "r"(s), "l"(g));
}
#define CP_COMMIT() asm volatile("cp.async.commit_group;")
#define CP_WAIT1() asm volatile("cp.async.wait_group 1;")
#define CP_WAIT0() asm volatile("cp.async.wait_group 0;")

// ---------------- scratch ----------------
__device__ float g_q[BT_ * HD_];
__device__ float g_k[BT_ * HD_];
__device__ float g_w[H_ * B_ * T_ * T_];
__device__ __align__(16) __nv_bfloat16 g_adjbh[N_ * N_];               // [n][k]
__device__ __align__(16) __nv_bfloat16 g_adjbl[N_ * N_];
__device__ __align__(16) __nv_bfloat16 g_sigbh[BT_ * C_ * N_];         // [(bt,c)][n]
__device__ __align__(16) __nv_bfloat16 g_sigbl[BT_ * C_ * N_];
__device__ __align__(16) __nv_bfloat16 g_aggbh[(size_t)BT_ * N_ * C_]; // [bt][n][c]
__device__ __align__(16) __nv_bfloat16 g_aggbl[(size_t)BT_ * N_ * C_];
__device__ __align__(16) __nv_bfloat16 g_wkbh[(size_t)B_ * 768 * 768]; // [b][(q,c)][(t,k)]
__device__ __align__(16) __nv_bfloat16 g_wkbl[(size_t)B_ * 768 * 768];
__device__ unsigned long long g_states[(N_ / 2) * BT_];
__device__ unsigned long long g_wqs[(N_ / 2) * HD_];
__device__ unsigned long long g_wks[(N_ / 2) * HD_];
__device__ float g_kwf[T_ * H_ * C_ * C_];
__device__ float g_kgws[T_ * H_ * C_];
__device__ float g_bgwf[T_ * H_ * C_];
__device__ float g_bgws[T_ * H_];
__device__ float g_kws[B_ * T_ * T_ * C_];
__device__ float g_bgf[B_ * T_ * C_];
__device__ float g_stb[B_ * T_];
__device__ double g_part[B_ * 96 * 2];
__device__ float g_stats[B_ * 4];

// stage: 4 planes (Ah,Al,Bh,Bl), each 128 rows x 64B data, 80B stride
#define PL 10240
#define STB 40960

// ---------------- presplits ----------------
__global__ void presplit_adj_kernel(const float* __restrict__ adj) {
    int idx = blockIdx.x * 256 + threadIdx.x;
    __nv_bfloat16 h, l;
    split1(adj[idx], h, l);
    g_adjbh[idx] = h; g_adjbl[idx] = l;
}
__global__ void presplit_sig_kernel(const float* __restrict__ sig) {
    __shared__ float s[32][65];
    int bt = blockIdx.y, n0 = blockIdx.x * 32;
    int tid = threadIdx.x;
#pragma unroll
    for (int p = 0; p < 8; p++) {
        int e = tid + p * 256;
        int n = e >> 6, c = e & 63;
        s[n][c] = sig[((size_t)bt * N_ + n0 + n) * C_ + c];
    }
    __syncthreads();
#pragma unroll
    for (int p = 0; p < 8; p++) {
        int e = tid + p * 256;
        int c = e >> 5, n = e & 31;
        __nv_bfloat16 h, l;
        split1(s[n][c], h, l);
        size_t o = ((size_t)bt * C_ + c) * N_ + n0 + n;
        g_sigbh[o] = h; g_sigbl[o] = l;
    }
}
__global__ void presplit_w_kernel(const float* __restrict__ Wq,
                                  const float* __restrict__ Wk) {
    int idx = blockIdx.x * 256 + threadIdx.x;
    int kp = idx / HD_, m = idx % HD_;
    const float* W = blockIdx.y ? Wk : Wq;
    unsigned long long* o = blockIdx.y ? g_wks : g_wqs;
    o[idx] = splitpack(W[(size_t)(2 * kp) * HD_ + m], W[(size_t)(2 * kp + 1) * HD_ + m]);
}
__global__ void presplit_state_kernel(const float* __restrict__ state) {
    int idx = blockIdx.x * 256 + threadIdx.x;
    int kp = idx / BT_, bt = idx % BT_;
    g_states[idx] = splitpack(state[(size_t)bt * N_ + 2 * kp],
                              state[(size_t)bt * N_ + 2 * kp + 1]);
}

// ---------------- qkT (mma.sync) ----------------
__global__ void __launch_bounds__(256) qkT_kernel(const float* __restrict__ bq,
                                                  const float* __restrict__ bk) {
    __shared__ unsigned Ah[16][104], Al[16][104], Bh[16][72], Bl[16][72];
    int j0 = blockIdx.x * 64;
    int isk = blockIdx.y;
    const unsigned long long* W = isk ? g_wks : g_wqs;
    int tid = threadIdx.x, lane = tid & 31, wc = tid >> 5;
    int lq = lane >> 2, lr = lane & 3;
    float acc[6][4];
#pragma unroll
    for (int i = 0; i < 6; i++)
#pragma unroll
        for (int r = 0; r < 4; r++) acc[i][r] = 0.f;
    for (int kc = 0; kc < 32; kc++) {
        int kp0 = kc * 16;
#pragma unroll
        for (int p = 0; p < 6; p++) {
            int e = tid + p * 256;
            int kp = e & 15, m = e >> 4;
            unsigned long long v = g_states[(size_t)(kp0 + kp) * BT_ + m];
            Ah[kp][m] = (unsigned)v; Al[kp][m] = (unsigned)(v >> 32);
        }
#pragma unroll
        for (int p = 0; p < 4; p++) {
            int e = tid + p * 256;
            int kp = e >> 6, jf = e & 63;
            unsigned long long v = W[(size_t)(kp0 + kp) * HD_ + j0 + jf];
            Bh[kp][jf] = (unsigned)v; Bl[kp][jf] = (unsigned)(v >> 32);
        }
        __syncthreads();
#pragma unroll
        for (int ks = 0; ks < 2; ks++) {
            int kb = ks * 8, col = wc * 8 + lq;
            unsigned bh0 = Bh[kb + lr][col], bh1 = Bh[kb + lr + 4][col];
            unsigned bl0 = Bl[kb + lr][col], bl1 = Bl[kb + lr + 4][col];
#pragma unroll
            for (int i = 0; i < 6; i++) {
                int m = i * 16 + lq;
                unsigned ah0 = Ah[kb + lr][m],     ah1 = Ah[kb + lr][m + 8];
                unsigned ah2 = Ah[kb + lr + 4][m], ah3 = Ah[kb + lr + 4][m + 8];
                unsigned al0 = Al[kb + lr][m],     al1 = Al[kb + lr][m + 8];
                unsigned al2 = Al[kb + lr + 4][m], al3 = Al[kb + lr + 4][m + 8];
                mma16816(acc[i], ah0, ah1, ah2, ah3, bh0, bh1);
                mma16816(acc[i], ah0, ah1, ah2, ah3, bl0, bl1);
                mma16816(acc[i], al0, al1, al2, al3, bh0, bh1);
            }
        }
        __syncthreads();
    }
    const float* bias = isk ? bk : bq;
    float* out = isk ? g_k : g_q;
    int col = j0 + wc * 8 + lr * 2;
    float b0 = bias[col], b1 = bias[col + 1];
#pragma unroll
    for (int i = 0; i < 6; i++) {
        int row = i * 16 + lq;
        *(float2*)(out + (size_t)row * HD_ + col) = make_float2(acc[i][0] + b0, acc[i][1] + b1);
        *(float2*)(out + (size_t)(row + 8) * HD_ + col) = make_float2(acc[i][2] + b0, acc[i][3] + b1);
    }
}

// ---------------- attw ----------------
__global__ void attw_kernel() {
    __shared__ float sc[T_][T_];
    int b = blockIdx.x % B_, h = blockIdx.x / B_;
    int t = threadIdx.x;
    int i = t / T_, j = t % T_;
    if (t < T_ * T_) {
        const float* qp = &g_q[(b * T_ + i) * HD_ + h * D_];
        const float* kp = &g_k[(b * T_ + j) * HD_ + h * D_];
        float d = 0.f;
#pragma unroll
        for (int x = 0; x < D_; x++) d = fmaf(qp[x], kp[x], d);
        sc[i][j] = d * 0.125f;
    }
    __syncthreads();
    if (t < T_ * T_) {
        float mx = -1e30f;
#pragma unroll
        for (int x = 0; x < T_; x++) mx = fmaxf(mx, sc[i][x]);
        float sm = 0.f;
#pragma unroll
        for (int x = 0; x < T_; x++) sm += expf(sc[i][x] - mx);
        g_w[((h * B_ + b) * T_ + i) * T_ + j] = expf(sc[i][j] - mx) / sm;
    }
}

// ---------------- kwf ----------------
__global__ void kwf_kernel(const float* __restrict__ Kg, const float* __restrict__ Wf,
                           const float* __restrict__ Ws, const float* __restrict__ bg) {
    __shared__ float sKg[64][65], sWf[64][66], sWs[64], sbg[64];
    int t = blockIdx.x / H_, h = blockIdx.x % H_;
    int tid = threadIdx.x;
#pragma unroll
    for (int p = 0; p < 16; p++) {
        int e = tid + p * 256;
        int cp = e >> 6, k = e & 63;
        sKg[cp][k] = Kg[((size_t)t * C_ + cp) * HD_ + h * D_ + k];
        sWf[cp][k] = Wf[(size_t)(h * D_ + cp) * C_ + k];
    }
    if (tid < 64) { sWs[tid] = Ws[h * D_ + tid]; sbg[tid] = bg[t * HD_ + h * D_ + tid]; }
    __syncthreads();
    int cp = tid >> 2, cg = (tid & 3) * 16;
    float acc[16];
#pragma unroll
    for (int j = 0; j < 16; j++) acc[j] = 0.f;
    for (int k = 0; k < 64; k++) {
        float a = sKg[cp][k];
#pragma unroll
        for (int j = 0; j < 16; j++) acc[j] = fmaf(a, sWf[k][cg + j], acc[j]);
    }
    float* o = g_kwf + (((size_t)t * H_ + h) * C_ + cp) * C_ + cg;
#pragma unroll
    for (int j = 0; j < 16; j++) o[j] = acc[j];
    if (tid < 64) {
        float s = 0.f;
        for (int k = 0; k < 64; k++) s = fmaf(sKg[tid][k], sWs[k], s);
        g_kgws[((size_t)t * H_ + h) * C_ + tid] = s;
    } else if (tid < 128) {
        int c = tid - 64;
        float s = 0.f;
        for (int k = 0; k < 64; k++) s = fmaf(sbg[k], sWf[k][c], s);
        g_bgwf[((size_t)t * H_ + h) * C_ + c] = s;
    } else if (tid == 128) {
        float s = 0.f;
        for (int k = 0; k < 64; k++) s = fmaf(sbg[k], sWs[k], s);
        g_bgws[t * H_ + h] = s;
    }
}

// ---------------- wk5 ----------------
__global__ void wk5_kernel() {
    __shared__ float sw[H_];
    __shared__ float sv[64][65];
    int blk = blockIdx.x;
    int t = blk % T_;
    int bq = blk / T_;
    int q = bq % T_, b = bq / T_;
    int tid = threadIdx.x;
    if (tid < H_) sw[tid] = g_w[((tid * B_ + b) * T_ + q) * T_ + t];
    __syncthreads();
#pragma unroll
    for (int p = 0; p < 16; p++) {
        int idx = tid + p * 256;
        int k = idx >> 6, c = idx & 63;
        float s = 0.f;
#pragma unroll
        for (int h = 0; h < H_; h++)
            s = fmaf(sw[h], g_kwf[(((size_t)t * H_ + h) * C_ + k) * C_ + c], s);
        sv[k][c] = s;
    }
    __syncthreads();
#pragma unroll
    for (int p = 0; p < 16; p++) {
        int idx = tid + p * 256;
        int c = idx >> 6, k = idx & 63;
        __nv_bfloat16 h, l;
        split1(sv[k][c], h, l);
        size_t o = ((size_t)b * 768 + q * 64 + c) * 768 + t * 64 + k;
        g_wkbh[o] = h; g_wkbl[o] = l;
    }
}

// ---------------- mix ----------------
__global__ void mix_kernel() {
    __shared__ float sw2[H_ * T_];
    int bq = blockIdx.x;
    int q = bq % T_, b = bq / T_;
    int tid = threadIdx.x;
    if (tid < H_ * T_) {
        int h = tid / T_, t = tid % T_;
        sw2[tid] = g_w[((h * B_ + b) * T_ + q) * T_ + t];
    }
    __syncthreads();
    for (int idx = tid; idx < T_ * C_; idx += 128) {
        int t = idx >> 6, cp = idx & 63;
        float s = 0.f;
#pragma unroll
        for (int h = 0; h < H_; h++)
            s = fmaf(sw2[h * T_ + t], g_kgws[((size_t)t * H_ + h) * C_ + cp], s);
        g_kws[((size_t)bq * T_ + t) * C_ + cp] = s;
    }
    if (tid < C_) {
        float s = 0.f;
        for (int t = 0; t < T_; t++)
#pragma unroll
            for (int h = 0; h < H_; h++)
                s = fmaf(sw2[h * T_ + t], g_bgwf[((size_t)t * H_ + h) * C_ + tid], s);
        g_bgf[(size_t)bq * C_ + tid] = s;
    } else if (tid == 64) {
        float s = 0.f;
        for (int t = 0; t < T_; t++)
            for (int h = 0; h < H_; h++)
                s = fmaf(sw2[h * T_ + t], g_bgws[t * H_ + h], s);
        g_stb[bq] = s;
    }
}

// ---------------- GEMM1: agg = adj @ sig_cat (cp.async + ldmatrix) ----------------
__global__ void __launch_bounds__(256, 2) aggT6_kernel() {
    extern __shared__ unsigned char sm8[];
    unsigned sbase = smem_u32addr(sm8);
    int j0 = blockIdx.x * 128, n0 = blockIdx.y * 128;
    int tid = threadIdx.x, lane = tid & 31, wid = tid >> 5;
    int wm = (wid & 1) * 64, wn = (wid >> 1) * 32;
    int lq = lane >> 2, lr = lane & 3;
    int frow = (lane & 7) + ((lane >> 3) & 1) * 8;
    int fkoff = (lane >> 4) * 16;

    auto load_stage = [&](int st, int kc) {
        int k0 = kc * 32;
        unsigned so = sbase + st * STB;
#pragma unroll
        for (int p = 0; p < 8; p++) {
            int e = tid + p * 256;
            int pl = e >> 9;
            int idx = e & 511;
            int r = idx >> 2, c16 = idx & 3;
            unsigned dst = so + pl * PL + r * 80 + c16 * 16;
            const __nv_bfloat16* src;
            if (pl == 0)      src = g_adjbh + (size_t)(n0 + r) * N_ + k0 + c16 * 8;
            else if (pl == 1) src = g_adjbl + (size_t)(n0 + r) * N_ + k0 + c16 * 8;
            else if (pl == 2) src = g_sigbh + (size_t)(j0 + r) * N_ + k0 + c16 * 8;
            else              src = g_sigbl + (size_t)(j0 + r) * N_ + k0 + c16 * 8;
            cpasync16(dst, src);
        }
        CP_COMMIT();
    };

    float acc[4][4][4];
#pragma unroll
    for (int i = 0; i < 4; i++)
#pragma unroll
        for (int j = 0; j < 4; j++)
#pragma unroll
            for (int r = 0; r < 4; r++) acc[i][j][r] = 0.f;

    load_stage(0, 0);
    for (int kc = 0; kc < 32; kc++) {
        int cur = kc & 1;
        if (kc < 31) { load_stage(cur ^ 1, kc + 1); CP_WAIT1(); }
        else CP_WAIT0();
        __syncthreads();
        unsigned A0 = sbase + cur * STB;
        unsigned B0 = A0 + 2 * PL;
#pragma unroll
        for (int ks = 0; ks < 2; ks++) {
            int kb = ks * 32;
            unsigned bh[4][2], bl[4][2];
#pragma unroll
            for (int jj = 0; jj < 2; jj++) {
                unsigned baddr = B0 + (wn + jj * 16 + frow) * 80 + kb + fkoff;
                unsigned r0, r1, r2, r3;
                ldsm_x4(r0, r1, r2, r3, baddr);
                bh[jj * 2][0] = r0; bh[jj * 2 + 1][0] = r1;
                bh[jj * 2][1] = r2; bh[jj * 2 + 1][1] = r3;
                ldsm_x4(r0, r1, r2, r3, baddr + PL);
                bl[jj * 2][0] = r0; bl[jj * 2 + 1][0] = r1;
                bl[jj * 2][1] = r2; bl[jj * 2 + 1][1] = r3;
            }
#pragma unroll
            for (int i = 0; i < 4; i++) {
                unsigned aaddr = A0 + (wm + i * 16 + frow) * 80 + kb + fkoff;
                unsigned ah0, ah1, ah2, ah3, al0, al1, al2, al3;
                ldsm_x4(ah0, ah1, ah2, ah3, aaddr);
                ldsm_x4(al0, al1, al2, al3, aaddr + PL);
#pragma unroll
                for (int j = 0; j < 4; j++) {
                    mma16816(acc[i][j], ah0, ah1, ah2, ah3, bh[j][0], bh[j][1]);
                    mma16816(acc[i][j], ah0, ah1, ah2, ah3, bl[j][0], bl[j][1]);
                    mma16816(acc[i][j], al0, al1, al2, al3, bh[j][0], bh[j][1]);
                }
            }
        }
        __syncthreads();
    }
    // epilogue: split -> agg bf16 planes [bt][n][c]
#pragma unroll
    for (int i = 0; i < 4; i++) {
        int row = n0 + wm + i * 16 + lq;
#pragma unroll
        for (int j = 0; j < 4; j++) {
            int jcol = j0 + wn + j * 8 + lr * 2;
            int bt = jcol >> 6, c = jcol & 63;
            __nv_bfloat16 h0, l0, h1, l1;
            split1(acc[i][j][0], h0, l0);
            split1(acc[i][j][1], h1, l1);
            size_t o = ((size_t)bt * N_ + row) * C_ + c;
            *(__nv_bfloat162*)(g_aggbh + o) = __halves2bfloat162(h0, h1);
            *(__nv_bfloat162*)(g_aggbl + o) = __halves2bfloat162(l0, l1);
            split1(acc[i][j][2], h0, l0);
            split1(acc[i][j][3], h1, l1);
            o = ((size_t)bt * N_ + row + 8) * C_ + c;
            *(__nv_bfloat162*)(g_aggbh + o) = __halves2bfloat162(h0, h1);
            *(__nv_bfloat162*)(g_aggbl + o) = __halves2bfloat162(l0, l1);
        }
    }
}

// ---------------- GEMM2: fused signal (cp.async + ldmatrix) ----------------
__global__ void __launch_bounds__(256, 2) fusedsig6_kernel(
    const float* __restrict__ bf, const float* __restrict__ sig,
    float* __restrict__ out_sig) {
    extern __shared__ unsigned char sm8[];
    unsigned sbase = smem_u32addr(sm8);
    int j0 = blockIdx.x * 128, n0 = blockIdx.y * 128;
    int b = blockIdx.z;
    int tid = threadIdx.x, lane = tid & 31, wid = tid >> 5;
    int wm = (wid & 1) * 64, wn = (wid >> 1) * 32;
    int lq = lane >> 2, lr = lane & 3;
    int frow = (lane & 7) + ((lane >> 3) & 1) * 8;
    int fkoff = (lane >> 4) * 16;

    auto load_stage = [&](int st, int kc) {
        int t = kc >> 1;
        int kloc = (kc & 1) * 32;
        unsigned so = sbase + st * STB;
#pragma unroll
        for (int p = 0; p < 8; p++) {
            int e = tid + p * 256;
            int pl = e >> 9;
            int idx = e & 511;
            int r = idx >> 2, c16 = idx & 3;
            unsigned dst = so + pl * PL + r * 80 + c16 * 16;
            const __nv_bfloat16* src;
            if (pl == 0)
                src = g_aggbh + ((size_t)(b * T_ + t) * N_ + n0 + r) * C_ + kloc + c16 * 8;
            else if (pl == 1)
                src = g_aggbl + ((size_t)(b * T_ + t) * N_ + n0 + r) * C_ + kloc + c16 * 8;
            else if (pl == 2)
                src = g_wkbh + ((size_t)b * 768 + j0 + r) * 768 + kc * 32 + c16 * 8;
            else
                src = g_wkbl + ((size_t)b * 768 + j0 + r) * 768 + kc * 32 + c16 * 8;
            cpasync16(dst, src);
        }
        CP_COMMIT();
    };

    float acc[4][4][4];
#pragma unroll
    for (int i = 0; i < 4; i++)
#pragma unroll
        for (int j = 0; j < 4; j++)
#pragma unroll
            for (int r = 0; r < 4; r++) acc[i][j][r] = 0.f;

    load_stage(0, 0);
    for (int kc = 0; kc < 24; kc++) {
        int cur = kc & 1;
        if (kc < 23) { load_stage(cur ^ 1, kc + 1); CP_WAIT1(); }
        else CP_WAIT0();
        __syncthreads();
        unsigned A0 = sbase + cur * STB;
        unsigned B0 = A0 + 2 * PL;
#pragma unroll
        for (int ks = 0; ks < 2; ks++) {
            int kb = ks * 32;
            unsigned bh[4][2], bl[4][2];
#pragma unroll
            for (int jj = 0; jj < 2; jj++) {
                unsigned baddr = B0 + (wn + jj * 16 + frow) * 80 + kb + fkoff;
                unsigned r0, r1, r2, r3;
                ldsm_x4(r0, r1, r2, r3, baddr);
                bh[jj * 2][0] = r0; bh[jj * 2 + 1][0] = r1;
                bh[jj * 2][1] = r2; bh[jj * 2 + 1][1] = r3;
                ldsm_x4(r0, r1, r2, r3, baddr + PL);
                bl[jj * 2][0] = r0; bl[jj * 2 + 1][0] = r1;
                bl[jj * 2][1] = r2; bl[jj * 2 + 1][1] = r3;
            }
#pragma unroll
            for (int i = 0; i < 4; i++) {
                unsigned aaddr = A0 + (wm + i * 16 + frow) * 80 + kb + fkoff;
                unsigned ah0, ah1, ah2, ah3, al0, al1, al2, al3;
                ldsm_x4(ah0, ah1, ah2, ah3, aaddr);
                ldsm_x4(al0, al1, al2, al3, aaddr + PL);
#pragma unroll
                for (int j = 0; j < 4; j++) {
                    mma16816(acc[i][j], ah0, ah1, ah2, ah3, bh[j][0], bh[j][1]);
                    mma16816(acc[i][j], ah0, ah1, ah2, ah3, bl[j][0], bl[j][1]);
                    mma16816(acc[i][j], al0, al1, al2, al3, bh[j][0], bh[j][1]);
                }
            }
        }
        __syncthreads();
    }
#pragma unroll
    for (int i = 0; i < 4; i++) {
        int row = n0 + wm + i * 16 + lq;
#pragma unroll
        for (int j = 0; j < 4; j++) {
            int jcol = j0 + wn + j * 8 + lr * 2;
            int q = jcol >> 6, c = jcol & 63;
            float2 bgf2 = *(const float2*)(g_bgf + (size_t)(b * T_ + q) * C_ + c);
            float2 bf2 = *(const float2*)(bf + c);
            float bb0 = bgf2.x + bf2.x, bb1 = bgf2.y + bf2.y;
            size_t o0 = ((size_t)(b * T_ + q) * N_ + row) * C_ + c;
            size_t o1 = ((size_t)(b * T_ + q) * N_ + row + 8) * C_ + c;
            float2 sg0 = *(const float2*)(sig + o0);
            float2 sg1 = *(const float2*)(sig + o1);
            *(float2*)(out_sig + o0) =
                make_float2(fmaxf(acc[i][j][0] + bb0, 0.f) + sg0.x,
                            fmaxf(acc[i][j][1] + bb1, 0.f) + sg0.y);
            *(float2*)(out_sig + o1) =
                make_float2(fmaxf(acc[i][j][2] + bb0, 0.f) + sg1.x,
                            fmaxf(acc[i][j][3] + bb1, 0.f) + sg1.y);
        }
    }
}

// ---------------- fused state ----------------
__global__ void fusedstate_kernel(const float* __restrict__ state,
                                  const float* __restrict__ bs,
                                  float* __restrict__ out_state) {
    __shared__ float sagg[128][67];
    __shared__ float skt[T_][C_];
    __shared__ float sstb[T_];
    int n0 = blockIdx.x * 128;
    int b = blockIdx.y;
    int tid = threadIdx.x;
    if (tid < T_) sstb[tid] = g_stb[b * T_ + tid];
    float st[T_];
#pragma unroll
    for (int q = 0; q < T_; q++) st[q] = 0.f;
    for (int t = 0; t < T_; t++) {
        __syncthreads();
#pragma unroll
        for (int p = 0; p < 32; p++) {
            int idx = tid + p * 128;
            int n = idx >> 5, c2 = (idx & 31) * 2;
            size_t g = ((size_t)(b * T_ + t) * N_ + n0 + n) * C_ + c2;
            __nv_bfloat162 h = *(const __nv_bfloat162*)(g_aggbh + g);
            __nv_bfloat162 l = *(const __nv_bfloat162*)(g_aggbl + g);
            sagg[n][c2] = __bfloat162float(__low2bfloat16(h)) + __bfloat162float(__low2bfloat16(l));
            sagg[n][c2 + 1] = __bfloat162float(__high2bfloat16(h)) + __bfloat162float(__high2bfloat16(l));
        }
#pragma unroll
        for (int p = 0; p < 6; p++) {
            int idx = tid + p * 128;
            int q = idx >> 6, cp = idx & 63;
            skt[q][cp] = g_kws[((size_t)(b * T_ + q) * T_ + t) * C_ + cp];
        }
        __syncthreads();
#pragma unroll 8
        for (int c = 0; c < C_; c++) {
            float a = sagg[tid][c];
#pragma unroll
            for (int q = 0; q < T_; q++) st[q] = fmaf(a, skt[q][c], st[q]);
        }
    }
    __syncthreads();
#pragma unroll
    for (int q = 0; q < T_; q++) {
        size_t idx = (size_t)(b * T_ + q) * N_ + n0 + tid;
        out_state[idx] = state[idx] + fmaxf(st[q] + sstb[q] + bs[0], 0.f);
    }
}

// ---------------- LayerNorm stats + normalization ----------------
__global__ void red_state_kernel(const float* __restrict__ ys) {
    __shared__ double ss[256], sq[256];
    int b = blockIdx.x;
    int tid = threadIdx.x;
    double s = 0, q = 0;
    for (int i = tid; i < T_ * N_; i += 256) {
        double x = ys[b * T_ * N_ + i];
        s += x; q += x * x;
    }
    ss[tid] = s; sq[tid] = q;
    __syncthreads();
    for (int o = 128; o; o >>= 1) {
        if (tid < o) { ss[tid] += ss[tid + o]; sq[tid] += sq[tid + o]; }
        __syncthreads();
    }
    if (tid == 0) {
        double cnt = (double)(T_ * N_);
        double mean = ss[0] / cnt;
        double var = sq[0] / cnt - mean * mean;
        g_stats[b * 4 + 0] = (float)mean;
        g_stats[b * 4 + 1] = rsqrtf((float)var + EPSV);
    }
}
__global__ void red_sig1_kernel(const float* __restrict__ yg) {
    __shared__ double ss[256], sq[256];
    int b = blockIdx.y, blk = blockIdx.x;
    int tid = threadIdx.x;
    const float* base = yg + (size_t)b * (T_ * N_ * C_) + blk * 8192;
    double s = 0, q = 0;
    for (int i = tid; i < 8192; i += 256) {
        double x = base[i];
        s += x; q += x * x;
    }
    ss[tid] = s; sq[tid] = q;
    __syncthreads();
    for (int o = 128; o; o >>= 1) {
        if (tid < o) { ss[tid] += ss[tid + o]; sq[tid] += sq[tid + o]; }
        __syncthreads();
    }
    if (tid == 0) {
        g_part[(b * 96 + blk) * 2 + 0] = ss[0];
        g_part[(b * 96 + blk) * 2 + 1] = sq[0];
    }
}
__global__ void red_sig2_kernel() {
    __shared__ double ss[128], sq[128];
    int b = blockIdx.x;
    int tid = threadIdx.x;
    double s = 0, q = 0;
    if (tid < 96) {
        s = g_part[(b * 96 + tid) * 2 + 0];
        q = g_part[(b * 96 + tid) * 2 + 1];
    }
    ss[tid] = s; sq[tid] = q;
    __syncthreads();
    for (int o = 64; o; o >>= 1) {
        if (tid < o) { ss[tid] += ss[tid + o]; sq[tid] += sq[tid + o]; }
        __syncthreads();
    }
    if (tid == 0) {
        double cnt = (double)T_ * N_ * C_;
        double mean = ss[0] / cnt;
        double var = sq[0] / cnt - mean * mean;
        g_stats[b * 4 + 2] = (float)mean;
        g_stats[b * 4 + 3] = rsqrtf((float)var + EPSV);
    }
}
__global__ void norm_state_kernel(float* __restrict__ ys,
                                  const float* __restrict__ gamma,
                                  const float* __restrict__ beta) {
    int idx = blockIdx.x * 256 + threadIdx.x;
    int b = idx / (T_ * N_);
    int r = idx % (T_ * N_);
    ys[idx] = (ys[idx] - g_stats[b * 4 + 0]) * g_stats[b * 4 + 1] * gamma[r] + beta[r];
}
__global__ void norm_sig_kernel(float* __restrict__ yg,
                                const float* __restrict__ gamma,
                                const float* __restrict__ beta) {
    int idx = blockIdx.x * 256 + threadIdx.x;
    int b = idx / (T_ * N_ * C_);
    int r = idx % (T_ * N_ * C_);
    yg[idx] = (yg[idx] - g_stats[b * 4 + 2]) * g_stats[b * 4 + 3] * gamma[r] + beta[r];
}

// ---------------- launch ----------------
extern "C" void kernel_launch(void* const* d_in, const int* in_sizes, int n_in,
                              void* d_out, int out_size) {
    const float* graph_state  = (const float*)d_in[0];
    const float* graph_signal = (const float*)d_in[1];
    const float* adj          = (const float*)d_in[2];
    const float* Wq           = (const float*)d_in[3];
    const float* bq           = (const float*)d_in[4];
    const float* Wk           = (const float*)d_in[5];
    const float* bk           = (const float*)d_in[6];
    const float* Kg           = (const float*)d_in[7];
    const float* bg           = (const float*)d_in[8];
    const float* Ws           = (const float*)d_in[9];
    const float* bs           = (const float*)d_in[10];
    const float* Wf           = (const float*)d_in[11];
    const float* bf           = (const float*)d_in[12];
    const float* gs_gamma     = (const float*)d_in[13];
    const float* gs_beta      = (const float*)d_in[14];
    const float* sg_gamma     = (const float*)d_in[15];
    const float* sg_beta      = (const float*)d_in[16];

    float* out_state  = (float*)d_out;
    float* out_signal = out_state + BT_ * N_;

    const int smem6 = 2 * STB;   // 81920 bytes
    cudaFuncSetAttribute(aggT6_kernel,
                         cudaFuncAttributeMaxDynamicSharedMemorySize, smem6);
    cudaFuncSetAttribute(fusedsig6_kernel,
                         cudaFuncAttributeMaxDynamicSharedMemorySize, smem6);

    presplit_adj_kernel<<<(N_ * N_) / 256, 256>>>(adj);
    presplit_sig_kernel<<<dim3(N_ / 32, BT_), 256>>>(graph_signal);
    presplit_w_kernel<<<dim3(((N_ / 2) * HD_) / 256, 2), 256>>>(Wq, Wk);
    presplit_state_kernel<<<((N_ / 2) * BT_) / 256, 256>>>(graph_state);
    qkT_kernel<<<dim3(8, 2), 256>>>(bq, bk);
    aggT6_kernel<<<dim3(48, 8), 256, smem6>>>();
    attw_kernel<<<H_ * B_, 160>>>();
    kwf_kernel<<<T_ * H_, 256>>>(Kg, Wf, Ws, bg);
    wk5_kernel<<<B_ * T_ * T_, 256>>>();
    mix_kernel<<<B_ * T_, 128>>>();
    fusedsig6_kernel<<<dim3(6, 8, B_), 256, smem6>>>(bf, graph_signal, out_signal);
    fusedstate_kernel<<<dim3(8, 8), 128>>>(graph_state, bs, out_state);
    red_state_kernel<<<B_, 256>>>(out_state);
    red_sig1_kernel<<<dim3(96, B_), 256>>>(out_signal);
    red_sig2_kernel<<<B_, 128>>>();
    norm_state_kernel<<<(BT_ * N_) / 256, 256>>>(out_state, gs_gamma, gs_beta);
    norm_sig_kernel<<<(BT_ * N_ * C_) / 256, 256>>>(out_signal, sg_gamma, sg_beta);
}

// round 16
// speedup vs baseline: 1.5091x; 1.5091x over previous
#include <cuda_runtime.h>
#include <cuda_bf16.h>

#define B_ 8
#define T_ 12
#define N_ 1024
#define C_ 64
#define H_ 8
#define D_ 64
#define HD_ 512
#define BT_ 96
#define EPSV 1e-3f

// ---------------- bf16 split + mma helpers ----------------
__device__ __forceinline__ void split2(float x0, float x1, unsigned& hi, unsigned& lo) {
    __nv_bfloat16 h0 = __float2bfloat16(x0);
    __nv_bfloat16 h1 = __float2bfloat16(x1);
    __nv_bfloat16 l0 = __float2bfloat16(x0 - __bfloat162float(h0));
    __nv_bfloat16 l1 = __float2bfloat16(x1 - __bfloat162float(h1));
    hi = ((unsigned)__bfloat16_as_ushort(h1) << 16) | (unsigned)__bfloat16_as_ushort(h0);
    lo = ((unsigned)__bfloat16_as_ushort(l1) << 16) | (unsigned)__bfloat16_as_ushort(l0);
}
__device__ __forceinline__ unsigned long long splitpack(float x0, float x1) {
    unsigned h, l;
    split2(x0, x1, h, l);
    return (unsigned long long)h | ((unsigned long long)l << 32);
}
__device__ __forceinline__ float comb_lo(unsigned h, unsigned l) {
    return __bfloat162float(__ushort_as_bfloat16((unsigned short)(h & 0xffff))) +
           __bfloat162float(__ushort_as_bfloat16((unsigned short)(l & 0xffff)));
}
__device__ __forceinline__ float comb_hi(unsigned h, unsigned l) {
    return __bfloat162float(__ushort_as_bfloat16((unsigned short)(h >> 16))) +
           __bfloat162float(__ushort_as_bfloat16((unsigned short)(l >> 16)));
}

__device__ __forceinline__ void mma16816(float* c, unsigned a0, unsigned a1,
                                         unsigned a2, unsigned a3,
                                         unsigned b0, unsigned b1) {
    asm volatile(
        "mma.sync.aligned.m16n8k16.row.col.f32.bf16.bf16.f32 "
        "{%0,%1,%2,%3},{%4,%5,%6,%7},{%8,%9},{%0,%1,%2,%3};"
        : "+f"(c[0]), "+f"(c[1]), "+f"(c[2]), "+f"(c[3])
        : "r"(a0), "r"(a1), "r"(a2), "r"(a3), "r"(b0), "r"(b1));
}

__device__ __forceinline__ unsigned smem_u32addr(const void* p) {
    unsigned a;
    asm("{.reg .u64 t; cvta.to.shared.u64 t, %1; cvt.u32.u64 %0, t;}" : "=r"(a) : "l"(p));
    return a;
}
__device__ __forceinline__ void cpasync16(unsigned saddr, const void* g) {
    asm volatile("cp.async.cg.shared.global [%0],[%1],16;" :: "r"(saddr), "l"(g));
}
#define CP_COMMIT() asm volatile("cp.async.commit_group;")
#define CP_WAIT2() asm volatile("cp.async.wait_group 2;")
#define CP_WAIT1() asm volatile("cp.async.wait_group 1;")
#define CP_WAIT0() asm volatile("cp.async.wait_group 0;")

// ---------------- scratch ----------------
__device__ float g_q[BT_ * HD_];
__device__ float g_k[BT_ * HD_];
__device__ float g_w[H_ * B_ * T_ * T_];
__device__ unsigned g_adjh[(N_ / 2) * N_];            // [kp][n]
__device__ unsigned g_adjl[(N_ / 2) * N_];
__device__ unsigned g_sigh[BT_ * (N_ / 2) * C_];      // [bt][kp][c]
__device__ unsigned g_sigl[BT_ * (N_ / 2) * C_];
__device__ unsigned g_aggh[(size_t)BT_ * 32 * N_];    // [bt][kp][n]
__device__ unsigned g_aggl[(size_t)BT_ * 32 * N_];
__device__ unsigned g_wk2h[(size_t)B_ * T_ * T_ * 2048];  // [(b,q,t)][kp*64+c]
__device__ unsigned g_wk2l[(size_t)B_ * T_ * T_ * 2048];
__device__ unsigned long long g_states[(N_ / 2) * BT_];
__device__ unsigned long long g_wqs[(N_ / 2) * HD_];
__device__ unsigned long long g_wks[(N_ / 2) * HD_];
__device__ float g_kwf[T_ * H_ * C_ * C_];
__device__ float g_kgws[T_ * H_ * C_];
__device__ float g_bgwf[T_ * H_ * C_];
__device__ float g_bgws[T_ * H_];
__device__ float g_kws[B_ * T_ * T_ * C_];
__device__ float g_bgf[B_ * T_ * C_];
__device__ float g_stb[B_ * T_];
__device__ double g_part[B_ * 96 * 2];
__device__ float g_stats[B_ * 4];

// stage layout (u32 units): Ah@0, Al@2176, Bh@4352, Bl@6528; stage stride 8704
#define STG 8704
#define AL_OFF 2176
#define BH_OFF 4352
#define BL_OFF 6528

// ---------------- 0) pre-split kernels ----------------
__global__ void presplit_adj_kernel(const float* __restrict__ adj) {
    int idx = blockIdx.x * 256 + threadIdx.x;      // kp*1024 + n
    int kp = idx >> 10, n = idx & 1023;
    unsigned h, l;
    split2(adj[(size_t)n * N_ + 2 * kp], adj[(size_t)n * N_ + 2 * kp + 1], h, l);
    g_adjh[idx] = h; g_adjl[idx] = l;
}
__global__ void presplit_sig_kernel(const float* __restrict__ sig) {
    int idx = blockIdx.x * 256 + threadIdx.x;      // (bt*(N/2)+kp)*64 + c
    int bt = idx / ((N_ / 2) * C_);
    int r = idx % ((N_ / 2) * C_);
    int kp = r / C_, c = r % C_;
    const float* s = sig + ((size_t)bt * N_ + 2 * kp) * C_ + c;
    unsigned h, l;
    split2(s[0], s[C_], h, l);
    g_sigh[idx] = h; g_sigl[idx] = l;
}
__global__ void presplit_w_kernel(const float* __restrict__ Wq,
                                  const float* __restrict__ Wk) {
    int idx = blockIdx.x * 256 + threadIdx.x;
    int kp = idx / HD_, m = idx % HD_;
    const float* W = blockIdx.y ? Wk : Wq;
    unsigned long long* o = blockIdx.y ? g_wks : g_wqs;
    o[idx] = splitpack(W[(size_t)(2 * kp) * HD_ + m], W[(size_t)(2 * kp + 1) * HD_ + m]);
}
__global__ void presplit_state_kernel(const float* __restrict__ state) {
    int idx = blockIdx.x * 256 + threadIdx.x;
    int kp = idx / BT_, bt = idx % BT_;
    g_states[idx] = splitpack(state[(size_t)bt * N_ + 2 * kp],
                              state[(size_t)bt * N_ + 2 * kp + 1]);
}

// ---------------- 1) q/k projections (tensor) ----------------
__global__ void __launch_bounds__(256) qkT_kernel(const float* __restrict__ bq,
                                                  const float* __restrict__ bk) {
    __shared__ unsigned Ah[16][104], Al[16][104], Bh[16][72], Bl[16][72];
    int j0 = blockIdx.x * 64;
    int isk = blockIdx.y;
    const unsigned long long* W = isk ? g_wks : g_wqs;
    int tid = threadIdx.x, lane = tid & 31, wc = tid >> 5;
    int lq = lane >> 2, lr = lane & 3;

    float acc[6][4];
#pragma unroll
    for (int i = 0; i < 6; i++)
#pragma unroll
        for (int r = 0; r < 4; r++) acc[i][r] = 0.f;

    for (int kc = 0; kc < 32; kc++) {
        int kp0 = kc * 16;
#pragma unroll
        for (int p = 0; p < 6; p++) {
            int e = tid + p * 256;
            int kp = e & 15, m = e >> 4;
            unsigned long long v = g_states[(size_t)(kp0 + kp) * BT_ + m];
            Ah[kp][m] = (unsigned)v; Al[kp][m] = (unsigned)(v >> 32);
        }
#pragma unroll
        for (int p = 0; p < 4; p++) {
            int e = tid + p * 256;
            int kp = e >> 6, jf = e & 63;
            unsigned long long v = W[(size_t)(kp0 + kp) * HD_ + j0 + jf];
            Bh[kp][jf] = (unsigned)v; Bl[kp][jf] = (unsigned)(v >> 32);
        }
        __syncthreads();
#pragma unroll
        for (int ks = 0; ks < 2; ks++) {
            int kb = ks * 8;
            int col = wc * 8 + lq;
            unsigned bh0 = Bh[kb + lr][col], bh1 = Bh[kb + lr + 4][col];
            unsigned bl0 = Bl[kb + lr][col], bl1 = Bl[kb + lr + 4][col];
#pragma unroll
            for (int i = 0; i < 6; i++) {
                int m = i * 16 + lq;
                unsigned ah0 = Ah[kb + lr][m],     ah1 = Ah[kb + lr][m + 8];
                unsigned ah2 = Ah[kb + lr + 4][m], ah3 = Ah[kb + lr + 4][m + 8];
                unsigned al0 = Al[kb + lr][m],     al1 = Al[kb + lr][m + 8];
                unsigned al2 = Al[kb + lr + 4][m], al3 = Al[kb + lr + 4][m + 8];
                mma16816(acc[i], ah0, ah1, ah2, ah3, bh0, bh1);
                mma16816(acc[i], ah0, ah1, ah2, ah3, bl0, bl1);
                mma16816(acc[i], al0, al1, al2, al3, bh0, bh1);
            }
        }
        __syncthreads();
    }
    const float* bias = isk ? bk : bq;
    float* out = isk ? g_k : g_q;
    int col = j0 + wc * 8 + lr * 2;
    float b0 = bias[col], b1 = bias[col + 1];
#pragma unroll
    for (int i = 0; i < 6; i++) {
        int row = i * 16 + lq;
        *(float2*)(out + (size_t)row * HD_ + col) =
            make_float2(acc[i][0] + b0, acc[i][1] + b1);
        *(float2*)(out + (size_t)(row + 8) * HD_ + col) =
            make_float2(acc[i][2] + b0, acc[i][3] + b1);
    }
}

// ---------------- 2) attention weights ----------------
__global__ void attw_kernel() {
    __shared__ float sc[T_][T_];
    int b = blockIdx.x % B_;
    int h = blockIdx.x / B_;
    int t = threadIdx.x;
    int i = t / T_, j = t % T_;
    if (t < T_ * T_) {
        const float* qp = &g_q[(b * T_ + i) * HD_ + h * D_];
        const float* kp = &g_k[(b * T_ + j) * HD_ + h * D_];
        float d = 0.f;
#pragma unroll
        for (int x = 0; x < D_; x++) d = fmaf(qp[x], kp[x], d);
        sc[i][j] = d * 0.125f;
    }
    __syncthreads();
    if (t < T_ * T_) {
        float mx = -1e30f;
#pragma unroll
        for (int x = 0; x < T_; x++) mx = fmaxf(mx, sc[i][x]);
        float sm = 0.f;
#pragma unroll
        for (int x = 0; x < T_; x++) sm += expf(sc[i][x] - mx);
        g_w[((h * B_ + b) * T_ + i) * T_ + j] = expf(sc[i][j] - mx) / sm;
    }
}

// ---------------- 3) per-(t,h) weight folds ----------------
__global__ void kwf_kernel(const float* __restrict__ Kg, const float* __restrict__ Wf,
                           const float* __restrict__ Ws, const float* __restrict__ bg) {
    __shared__ float sKg[64][65], sWf[64][66], sWs[64], sbg[64];
    int t = blockIdx.x / H_, h = blockIdx.x % H_;
    int tid = threadIdx.x;
#pragma unroll
    for (int p = 0; p < 16; p++) {
        int e = tid + p * 256;
        int cp = e >> 6, k = e & 63;
        sKg[cp][k] = Kg[((size_t)t * C_ + cp) * HD_ + h * D_ + k];
        sWf[cp][k] = Wf[(size_t)(h * D_ + cp) * C_ + k];
    }
    if (tid < 64) {
        sWs[tid] = Ws[h * D_ + tid];
        sbg[tid] = bg[t * HD_ + h * D_ + tid];
    }
    __syncthreads();
    int cp = tid >> 2, cg = (tid & 3) * 16;
    float acc[16];
#pragma unroll
    for (int j = 0; j < 16; j++) acc[j] = 0.f;
    for (int k = 0; k < 64; k++) {
        float a = sKg[cp][k];
#pragma unroll
        for (int j = 0; j < 16; j++) acc[j] = fmaf(a, sWf[k][cg + j], acc[j]);
    }
    float* o = g_kwf + (((size_t)t * H_ + h) * C_ + cp) * C_ + cg;
#pragma unroll
    for (int j = 0; j < 16; j++) o[j] = acc[j];
    if (tid < 64) {
        float s = 0.f;
        for (int k = 0; k < 64; k++) s = fmaf(sKg[tid][k], sWs[k], s);
        g_kgws[((size_t)t * H_ + h) * C_ + tid] = s;
    } else if (tid < 128) {
        int c = tid - 64;
        float s = 0.f;
        for (int k = 0; k < 64; k++) s = fmaf(sbg[k], sWf[k][c], s);
        g_bgwf[((size_t)t * H_ + h) * C_ + c] = s;
    } else if (tid == 128) {
        float s = 0.f;
        for (int k = 0; k < 64; k++) s = fmaf(sbg[k], sWs[k], s);
        g_bgws[t * H_ + h] = s;
    }
}

// ---------------- 4) WK planes ----------------
__global__ void wk_kernel() {
    __shared__ float sw[H_];
    int blk = blockIdx.x;
    int t = blk % T_;
    int bq = blk / T_;
    int q = bq % T_, b = bq / T_;
    int tid = threadIdx.x;
    if (tid < H_) sw[tid] = g_w[((tid * B_ + b) * T_ + q) * T_ + t];
    __syncthreads();
    unsigned* outh = g_wk2h + (size_t)blk * 2048;
    unsigned* outl = g_wk2l + (size_t)blk * 2048;
#pragma unroll
    for (int p = 0; p < 8; p++) {
        int idx = tid + p * 256;
        int kp = idx >> 6, c = idx & 63;
        float v0 = 0.f, v1 = 0.f;
#pragma unroll
        for (int h = 0; h < H_; h++) {
            const float* kw = g_kwf + ((size_t)t * H_ + h) * (C_ * C_);
            v0 = fmaf(sw[h], kw[(2 * kp) * C_ + c], v0);
            v1 = fmaf(sw[h], kw[(2 * kp + 1) * C_ + c], v1);
        }
        unsigned h2, l2;
        split2(v0, v1, h2, l2);
        outh[idx] = h2; outl[idx] = l2;
    }
}

// ---------------- 5) small mixes ----------------
__global__ void mix_kernel() {
    __shared__ float sw2[H_ * T_];
    int bq = blockIdx.x;
    int q = bq % T_, b = bq / T_;
    int tid = threadIdx.x;
    if (tid < H_ * T_) {
        int h = tid / T_, t = tid % T_;
        sw2[tid] = g_w[((h * B_ + b) * T_ + q) * T_ + t];
    }
    __syncthreads();
    for (int idx = tid; idx < T_ * C_; idx += 128) {
        int t = idx >> 6, cp = idx & 63;
        float s = 0.f;
#pragma unroll
        for (int h = 0; h < H_; h++)
            s = fmaf(sw2[h * T_ + t], g_kgws[((size_t)t * H_ + h) * C_ + cp], s);
        g_kws[((size_t)bq * T_ + t) * C_ + cp] = s;
    }
    if (tid < C_) {
        float s = 0.f;
        for (int t = 0; t < T_; t++)
#pragma unroll
            for (int h = 0; h < H_; h++)
                s = fmaf(sw2[h * T_ + t], g_bgwf[((size_t)t * H_ + h) * C_ + tid], s);
        g_bgf[(size_t)bq * C_ + tid] = s;
    } else if (tid == 64) {
        float s = 0.f;
        for (int t = 0; t < T_; t++)
            for (int h = 0; h < H_; h++)
                s = fmaf(sw2[h * T_ + t], g_bgws[t * H_ + h], s);
        g_stb[bq] = s;
    }
}

// ---------------- 6) agg = adj @ sig_cat (cp.async 3-stage) ----------------
__global__ void __launch_bounds__(256, 2) aggT_kernel() {
    extern __shared__ unsigned sm[];
    unsigned sbase = smem_u32addr(sm);
    int j0 = blockIdx.x * 128;
    int n0 = blockIdx.y * 128;
    int tid = threadIdx.x, lane = tid & 31, wid = tid >> 5;
    int wm = (wid & 1) * 64, wn = (wid >> 1) * 32;
    int lq = lane >> 2, lr = lane & 3;

    auto load_stage = [&](int stage, int kc) {
        int kp0 = kc * 16;
        unsigned so = sbase + stage * (STG * 4);
#pragma unroll
        for (int p = 0; p < 2; p++) {
            int e = tid + p * 256;
            int kp = e >> 5, mc = (e & 31) * 4;
            size_t ga = (size_t)(kp0 + kp) * N_;
            cpasync16(so + (kp * 136 + mc) * 4, g_adjh + ga + n0 + mc);
            cpasync16(so + (AL_OFF + kp * 136 + mc) * 4, g_adjl + ga + n0 + mc);
            int j = j0 + mc, bt = j >> 6, c = j & 63;
            size_t gb = ((size_t)bt * (N_ / 2) + kp0 + kp) * C_ + c;
            cpasync16(so + (BH_OFF + kp * 136 + mc) * 4, g_sigh + gb);
            cpasync16(so + (BL_OFF + kp * 136 + mc) * 4, g_sigl + gb);
        }
        CP_COMMIT();
    };

    float acc[4][4][4];
#pragma unroll
    for (int i = 0; i < 4; i++)
#pragma unroll
        for (int j = 0; j < 4; j++)
#pragma unroll
            for (int r = 0; r < 4; r++) acc[i][j][r] = 0.f;

    load_stage(0, 0);
    load_stage(1, 1);
    int cur = 0;
    for (int kc = 0; kc < 32; kc++) {
        if (kc + 2 < 32) { load_stage((cur + 2) % 3, kc + 2); CP_WAIT2(); }
        else if (kc + 1 < 32) CP_WAIT1();
        else CP_WAIT0();
        __syncthreads();
        const unsigned* Ah = sm + cur * STG;
        const unsigned* Al = Ah + AL_OFF;
        const unsigned* Bh = Ah + BH_OFF;
        const unsigned* Bl = Ah + BL_OFF;
#pragma unroll
        for (int ks = 0; ks < 2; ks++) {
            int kb = ks * 8;
            unsigned bh[4][2], bl[4][2];
#pragma unroll
            for (int j = 0; j < 4; j++) {
                int col = wn + j * 8 + lq;
                bh[j][0] = Bh[(kb + lr) * 136 + col];     bh[j][1] = Bh[(kb + lr + 4) * 136 + col];
                bl[j][0] = Bl[(kb + lr) * 136 + col];     bl[j][1] = Bl[(kb + lr + 4) * 136 + col];
            }
#pragma unroll
            for (int i = 0; i < 4; i++) {
                int m = wm + i * 16 + lq;
                unsigned ah0 = Ah[(kb + lr) * 136 + m],     ah1 = Ah[(kb + lr) * 136 + m + 8];
                unsigned ah2 = Ah[(kb + lr + 4) * 136 + m], ah3 = Ah[(kb + lr + 4) * 136 + m + 8];
                unsigned al0 = Al[(kb + lr) * 136 + m],     al1 = Al[(kb + lr) * 136 + m + 8];
                unsigned al2 = Al[(kb + lr + 4) * 136 + m], al3 = Al[(kb + lr + 4) * 136 + m + 8];
#pragma unroll
                for (int j = 0; j < 4; j++) {
                    mma16816(acc[i][j], ah0, ah1, ah2, ah3, bh[j][0], bh[j][1]);
                    mma16816(acc[i][j], ah0, ah1, ah2, ah3, bl[j][0], bl[j][1]);
                    mma16816(acc[i][j], al0, al1, al2, al3, bh[j][0], bh[j][1]);
                }
            }
        }
        __syncthreads();
        cur = (cur + 1) % 3;
    }
    // epilogue: write agg planes, k-major [bt][kp][n]
#pragma unroll
    for (int i = 0; i < 4; i++) {
        int row = n0 + wm + i * 16 + lq;
#pragma unroll
        for (int j = 0; j < 4; j++) {
            int jcol = j0 + wn + j * 8 + lr * 2;
            int bt = jcol >> 6, c2 = (jcol & 63) >> 1;
            size_t o = ((size_t)bt * 32 + c2) * N_;
            unsigned h, l;
            split2(acc[i][j][0], acc[i][j][1], h, l);
            g_aggh[o + row] = h; g_aggl[o + row] = l;
            split2(acc[i][j][2], acc[i][j][3], h, l);
            g_aggh[o + row + 8] = h; g_aggl[o + row + 8] = l;
        }
    }
}

// ---------------- 7) fused signal GEMM per b (cp.async 3-stage) ----------
__global__ void __launch_bounds__(256, 2) fusedsig2_kernel(
    const float* __restrict__ bf, const float* __restrict__ sig,
    float* __restrict__ out_sig) {
    extern __shared__ unsigned sm[];
    unsigned sbase = smem_u32addr(sm);
    int j0 = blockIdx.x * 128;
    int n0 = blockIdx.y * 128;
    int b = blockIdx.z;
    int tid = threadIdx.x, lane = tid & 31, wid = tid >> 5;
    int wm = (wid & 1) * 64, wn = (wid >> 1) * 32;
    int lq = lane >> 2, lr = lane & 3;

    auto load_stage = [&](int stage, int kc) {
        int kpg0 = kc * 16;
        int t = kpg0 >> 5;
        int kpl0 = kpg0 & 31;
        unsigned so = sbase + stage * (STG * 4);
#pragma unroll
        for (int p = 0; p < 2; p++) {
            int e = tid + p * 256;
            int kp = e >> 5, mc = (e & 31) * 4;
            size_t ga = ((size_t)(b * T_ + t) * 32 + kpl0 + kp) * N_ + n0 + mc;
            cpasync16(so + (kp * 136 + mc) * 4, g_aggh + ga);
            cpasync16(so + (AL_OFF + kp * 136 + mc) * 4, g_aggl + ga);
            int j = j0 + mc, q = j >> 6, c = j & 63;
            size_t gb = (((size_t)(b * T_ + q) * T_ + t) << 11) + (kpl0 + kp) * 64 + c;
            cpasync16(so + (BH_OFF + kp * 136 + mc) * 4, g_wk2h + gb);
            cpasync16(so + (BL_OFF + kp * 136 + mc) * 4, g_wk2l + gb);
        }
        CP_COMMIT();
    };

    float acc[4][4][4];
#pragma unroll
    for (int i = 0; i < 4; i++)
#pragma unroll
        for (int j = 0; j < 4; j++)
#pragma unroll
            for (int r = 0; r < 4; r++) acc[i][j][r] = 0.f;

    load_stage(0, 0);
    load_stage(1, 1);
    int cur = 0;
    for (int kc = 0; kc < 24; kc++) {
        if (kc + 2 < 24) { load_stage((cur + 2) % 3, kc + 2); CP_WAIT2(); }
        else if (kc + 1 < 24) CP_WAIT1();
        else CP_WAIT0();
        __syncthreads();
        const unsigned* Ah = sm + cur * STG;
        const unsigned* Al = Ah + AL_OFF;
        const unsigned* Bh = Ah + BH_OFF;
        const unsigned* Bl = Ah + BL_OFF;
#pragma unroll
        for (int ks = 0; ks < 2; ks++) {
            int kb = ks * 8;
            unsigned bh[4][2], bl[4][2];
#pragma unroll
            for (int j = 0; j < 4; j++) {
                int col = wn + j * 8 + lq;
                bh[j][0] = Bh[(kb + lr) * 136 + col];     bh[j][1] = Bh[(kb + lr + 4) * 136 + col];
                bl[j][0] = Bl[(kb + lr) * 136 + col];     bl[j][1] = Bl[(kb + lr + 4) * 136 + col];
            }
#pragma unroll
            for (int i = 0; i < 4; i++) {
                int m = wm + i * 16 + lq;
                unsigned ah0 = Ah[(kb + lr) * 136 + m],     ah1 = Ah[(kb + lr) * 136 + m + 8];
                unsigned ah2 = Ah[(kb + lr + 4) * 136 + m], ah3 = Ah[(kb + lr + 4) * 136 + m + 8];
                unsigned al0 = Al[(kb + lr) * 136 + m],     al1 = Al[(kb + lr) * 136 + m + 8];
                unsigned al2 = Al[(kb + lr + 4) * 136 + m], al3 = Al[(kb + lr + 4) * 136 + m + 8];
#pragma unroll
                for (int j = 0; j < 4; j++) {
                    mma16816(acc[i][j], ah0, ah1, ah2, ah3, bh[j][0], bh[j][1]);
                    mma16816(acc[i][j], ah0, ah1, ah2, ah3, bl[j][0], bl[j][1]);
                    mma16816(acc[i][j], al0, al1, al2, al3, bh[j][0], bh[j][1]);
                }
            }
        }
        __syncthreads();
        cur = (cur + 1) % 3;
    }
#pragma unroll
    for (int i = 0; i < 4; i++) {
        int row = n0 + wm + i * 16 + lq;
#pragma unroll
        for (int j = 0; j < 4; j++) {
            int jcol = j0 + wn + j * 8 + lr * 2;
            int q = jcol >> 6, c = jcol & 63;
            float2 bgf2 = *(const float2*)(g_bgf + (size_t)(b * T_ + q) * C_ + c);
            float2 bf2 = *(const float2*)(bf + c);
            float bb0 = bgf2.x + bf2.x, bb1 = bgf2.y + bf2.y;
            size_t o0 = ((size_t)(b * T_ + q) * N_ + row) * C_ + c;
            size_t o1 = ((size_t)(b * T_ + q) * N_ + row + 8) * C_ + c;
            float2 sg0 = *(const float2*)(sig + o0);
            float2 sg1 = *(const float2*)(sig + o1);
            *(float2*)(out_sig + o0) =
                make_float2(fmaxf(acc[i][j][0] + bb0, 0.f) + sg0.x,
                            fmaxf(acc[i][j][1] + bb1, 0.f) + sg0.y);
            *(float2*)(out_sig + o1) =
                make_float2(fmaxf(acc[i][j][2] + bb0, 0.f) + sg1.x,
                            fmaxf(acc[i][j][3] + bb1, 0.f) + sg1.y);
        }
    }
}

// ---------------- 8) fused state ----------------
__global__ void fusedstate_kernel(const float* __restrict__ state,
                                  const float* __restrict__ bs,
                                  float* __restrict__ out_state) {
    __shared__ float sagg[128][67];
    __shared__ float skt[T_][C_];
    __shared__ float sstb[T_];
    int n0 = blockIdx.x * 128;
    int b = blockIdx.y;
    int tid = threadIdx.x;
    if (tid < T_) sstb[tid] = g_stb[b * T_ + tid];
    float st[T_];
#pragma unroll
    for (int q = 0; q < T_; q++) st[q] = 0.f;

    for (int t = 0; t < T_; t++) {
        __syncthreads();
#pragma unroll
        for (int p = 0; p < 32; p++) {
            int idx = tid + p * 128;
            int kp = idx >> 7, n = idx & 127;
            size_t g = ((size_t)(b * T_ + t) * 32 + kp) * N_ + n0 + n;
            unsigned h = g_aggh[g], l = g_aggl[g];
            sagg[n][2 * kp] = comb_lo(h, l);
            sagg[n][2 * kp + 1] = comb_hi(h, l);
        }
#pragma unroll
        for (int p = 0; p < 6; p++) {
            int idx = tid + p * 128;
            int q = idx >> 6, cp = idx & 63;
            skt[q][cp] = g_kws[((size_t)(b * T_ + q) * T_ + t) * C_ + cp];
        }
        __syncthreads();
#pragma unroll 8
        for (int c = 0; c < C_; c++) {
            float a = sagg[tid][c];
#pragma unroll
            for (int q = 0; q < T_; q++) st[q] = fmaf(a, skt[q][c], st[q]);
        }
    }
    __syncthreads();
#pragma unroll
    for (int q = 0; q < T_; q++) {
        size_t idx = (size_t)(b * T_ + q) * N_ + n0 + tid;
        out_state[idx] = state[idx] + fmaxf(st[q] + sstb[q] + bs[0], 0.f);
    }
}

// ---------------- LayerNorm statistics ----------------
__global__ void red_state_kernel(const float* __restrict__ ys) {
    __shared__ double ss[256], sq[256];
    int b = blockIdx.x;
    int tid = threadIdx.x;
    double s = 0, q = 0;
    for (int i = tid; i < T_ * N_; i += 256) {
        double x = ys[b * T_ * N_ + i];
        s += x; q += x * x;
    }
    ss[tid] = s; sq[tid] = q;
    __syncthreads();
    for (int o = 128; o; o >>= 1) {
        if (tid < o) { ss[tid] += ss[tid + o]; sq[tid] += sq[tid + o]; }
        __syncthreads();
    }
    if (tid == 0) {
        double cnt = (double)(T_ * N_);
        double mean = ss[0] / cnt;
        double var = sq[0] / cnt - mean * mean;
        g_stats[b * 4 + 0] = (float)mean;
        g_stats[b * 4 + 1] = rsqrtf((float)var + EPSV);
    }
}

__global__ void red_sig1_kernel(const float* __restrict__ yg) {
    __shared__ double ss[256], sq[256];
    int b = blockIdx.y, blk = blockIdx.x;
    int tid = threadIdx.x;
    const float* base = yg + (size_t)b * (T_ * N_ * C_) + blk * 8192;
    double s = 0, q = 0;
    for (int i = tid; i < 8192; i += 256) {
        double x = base[i];
        s += x; q += x * x;
    }
    ss[tid] = s; sq[tid] = q;
    __syncthreads();
    for (int o = 128; o; o >>= 1) {
        if (tid < o) { ss[tid] += ss[tid + o]; sq[tid] += sq[tid + o]; }
        __syncthreads();
    }
    if (tid == 0) {
        g_part[(b * 96 + blk) * 2 + 0] = ss[0];
        g_part[(b * 96 + blk) * 2 + 1] = sq[0];
    }
}

__global__ void red_sig2_kernel() {
    __shared__ double ss[128], sq[128];
    int b = blockIdx.x;
    int tid = threadIdx.x;
    double s = 0, q = 0;
    if (tid < 96) {
        s = g_part[(b * 96 + tid) * 2 + 0];
        q = g_part[(b * 96 + tid) * 2 + 1];
    }
    ss[tid] = s; sq[tid] = q;
    __syncthreads();
    for (int o = 64; o; o >>= 1) {
        if (tid < o) { ss[tid] += ss[tid + o]; sq[tid] += sq[tid + o]; }
        __syncthreads();
    }
    if (tid == 0) {
        double cnt = (double)T_ * N_ * C_;
        double mean = ss[0] / cnt;
        double var = sq[0] / cnt - mean * mean;
        g_stats[b * 4 + 2] = (float)mean;
        g_stats[b * 4 + 3] = rsqrtf((float)var + EPSV);
    }
}

// ---------------- in-place normalization ----------------
__global__ void norm_state_kernel(float* __restrict__ ys,
                                  const float* __restrict__ gamma,
                                  const float* __restrict__ beta) {
    int idx = blockIdx.x * 256 + threadIdx.x;
    int b = idx / (T_ * N_);
    int r = idx % (T_ * N_);
    ys[idx] = (ys[idx] - g_stats[b * 4 + 0]) * g_stats[b * 4 + 1] * gamma[r] + beta[r];
}

__global__ void norm_sig_kernel(float* __restrict__ yg,
                                const float* __restrict__ gamma,
                                const float* __restrict__ beta) {
    int idx = blockIdx.x * 256 + threadIdx.x;
    int b = idx / (T_ * N_ * C_);
    int r = idx % (T_ * N_ * C_);
    yg[idx] = (yg[idx] - g_stats[b * 4 + 2]) * g_stats[b * 4 + 3] * gamma[r] + beta[r];
}

// ---------------- launch ----------------
extern "C" void kernel_launch(void* const* d_in, const int* in_sizes, int n_in,
                              void* d_out, int out_size) {
    const float* graph_state  = (const float*)d_in[0];
    const float* graph_signal = (const float*)d_in[1];
    const float* adj          = (const float*)d_in[2];
    const float* Wq           = (const float*)d_in[3];
    const float* bq           = (const float*)d_in[4];
    const float* Wk           = (const float*)d_in[5];
    const float* bk           = (const float*)d_in[6];
    const float* Kg           = (const float*)d_in[7];
    const float* bg           = (const float*)d_in[8];
    const float* Ws           = (const float*)d_in[9];
    const float* bs           = (const float*)d_in[10];
    const float* Wf           = (const float*)d_in[11];
    const float* bf           = (const float*)d_in[12];
    const float* gs_gamma     = (const float*)d_in[13];
    const float* gs_beta      = (const float*)d_in[14];
    const float* sg_gamma     = (const float*)d_in[15];
    const float* sg_beta      = (const float*)d_in[16];

    float* out_state  = (float*)d_out;
    float* out_signal = out_state + BT_ * N_;

    const int pipe_smem = 3 * STG * 4;   // 104448 bytes
    cudaFuncSetAttribute(aggT_kernel,
                         cudaFuncAttributeMaxDynamicSharedMemorySize, pipe_smem);
    cudaFuncSetAttribute(fusedsig2_kernel,
                         cudaFuncAttributeMaxDynamicSharedMemorySize, pipe_smem);

    presplit_adj_kernel<<<(N_ * N_ / 2) / 256, 256>>>(adj);
    presplit_sig_kernel<<<(BT_ * (N_ / 2) * C_) / 256, 256>>>(graph_signal);
    presplit_w_kernel<<<dim3(((N_ / 2) * HD_) / 256, 2), 256>>>(Wq, Wk);
    presplit_state_kernel<<<((N_ / 2) * BT_) / 256, 256>>>(graph_state);
    qkT_kernel<<<dim3(8, 2), 256>>>(bq, bk);
    attw_kernel<<<H_ * B_, 160>>>();
    kwf_kernel<<<T_ * H_, 256>>>(Kg, Wf, Ws, bg);
    wk_kernel<<<B_ * T_ * T_, 256>>>();
    mix_kernel<<<B_ * T_, 128>>>();
    aggT_kernel<<<dim3(48, 8), 256, pipe_smem>>>();
    fusedsig2_kernel<<<dim3(6, 8, B_), 256, pipe_smem>>>(bf, graph_signal, out_signal);
    fusedstate_kernel<<<dim3(8, 8), 128>>>(graph_state, bs, out_state);
    red_state_kernel<<<B_, 256>>>(out_state);
    red_sig1_kernel<<<dim3(96, B_), 256>>>(out_signal);
    red_sig2_kernel<<<B_, 128>>>();
    norm_state_kernel<<<(BT_ * N_) / 256, 256>>>(out_state, gs_gamma, gs_beta);
    norm_sig_kernel<<<(BT_ * N_ * C_) / 256, 256>>>(out_signal, sg_gamma, sg_beta);
}

// round 17
// speedup vs baseline: 1.5263x; 1.0114x over previous
#include <cuda_runtime.h>
#include <cuda_bf16.h>

#define B_ 8
#define T_ 12
#define N_ 1024
#define C_ 64
#define H_ 8
#define D_ 64
#define HD_ 512
#define BT_ 96
#define EPSV 1e-3f

// ---------------- bf16 split + mma helpers ----------------
__device__ __forceinline__ void split2(float x0, float x1, unsigned& hi, unsigned& lo) {
    __nv_bfloat16 h0 = __float2bfloat16(x0);
    __nv_bfloat16 h1 = __float2bfloat16(x1);
    __nv_bfloat16 l0 = __float2bfloat16(x0 - __bfloat162float(h0));
    __nv_bfloat16 l1 = __float2bfloat16(x1 - __bfloat162float(h1));
    hi = ((unsigned)__bfloat16_as_ushort(h1) << 16) | (unsigned)__bfloat16_as_ushort(h0);
    lo = ((unsigned)__bfloat16_as_ushort(l1) << 16) | (unsigned)__bfloat16_as_ushort(l0);
}
__device__ __forceinline__ unsigned long long splitpack(float x0, float x1) {
    unsigned h, l;
    split2(x0, x1, h, l);
    return (unsigned long long)h | ((unsigned long long)l << 32);
}
__device__ __forceinline__ float comb_lo(unsigned h, unsigned l) {
    return __bfloat162float(__ushort_as_bfloat16((unsigned short)(h & 0xffff))) +
           __bfloat162float(__ushort_as_bfloat16((unsigned short)(l & 0xffff)));
}
__device__ __forceinline__ float comb_hi(unsigned h, unsigned l) {
    return __bfloat162float(__ushort_as_bfloat16((unsigned short)(h >> 16))) +
           __bfloat162float(__ushort_as_bfloat16((unsigned short)(l >> 16)));
}

__device__ __forceinline__ void mma16816(float* c, unsigned a0, unsigned a1,
                                         unsigned a2, unsigned a3,
                                         unsigned b0, unsigned b1) {
    asm volatile(
        "mma.sync.aligned.m16n8k16.row.col.f32.bf16.bf16.f32 "
        "{%0,%1,%2,%3},{%4,%5,%6,%7},{%8,%9},{%0,%1,%2,%3};"
        : "+f"(c[0]), "+f"(c[1]), "+f"(c[2]), "+f"(c[3])
        : "r"(a0), "r"(a1), "r"(a2), "r"(a3), "r"(b0), "r"(b1));
}

__device__ __forceinline__ unsigned smem_u32addr(const void* p) {
    unsigned a;
    asm("{.reg .u64 t; cvta.to.shared.u64 t, %1; cvt.u32.u64 %0, t;}" : "=r"(a) : "l"(p));
    return a;
}
__device__ __forceinline__ void cpasync16(unsigned saddr, const void* g) {
    asm volatile("cp.async.cg.shared.global [%0],[%1],16;" :: "r"(saddr), "l"(g));
}
#define CP_COMMIT() asm volatile("cp.async.commit_group;")
#define CP_WAIT2() asm volatile("cp.async.wait_group 2;")
#define CP_WAIT1() asm volatile("cp.async.wait_group 1;")
#define CP_WAIT0() asm volatile("cp.async.wait_group 0;")

// ---------------- scratch ----------------
__device__ float g_q[BT_ * HD_];
__device__ float g_k[BT_ * HD_];
__device__ float g_w[H_ * B_ * T_ * T_];
__device__ unsigned g_adjh[(N_ / 2) * N_];            // [kp][n]
__device__ unsigned g_adjl[(N_ / 2) * N_];
__device__ unsigned g_sigh[BT_ * (N_ / 2) * C_];      // [bt][kp][c]
__device__ unsigned g_sigl[BT_ * (N_ / 2) * C_];
__device__ unsigned g_aggh[(size_t)BT_ * 32 * N_];    // [bt][kp][n]
__device__ unsigned g_aggl[(size_t)BT_ * 32 * N_];
__device__ unsigned g_wk2h[(size_t)B_ * T_ * T_ * 2048];  // [(b,q,t)][kp*64+c]
__device__ unsigned g_wk2l[(size_t)B_ * T_ * T_ * 2048];
__device__ unsigned long long g_states[(N_ / 2) * BT_];
__device__ unsigned long long g_wqs[(N_ / 2) * HD_];
__device__ unsigned long long g_wks[(N_ / 2) * HD_];
__device__ float g_kwf[T_ * H_ * C_ * C_];
__device__ float g_kgws[T_ * H_ * C_];
__device__ float g_bgwf[T_ * H_ * C_];
__device__ float g_bgws[T_ * H_];
__device__ float g_kws[B_ * T_ * T_ * C_];
__device__ float g_bgf[B_ * T_ * C_];
__device__ float g_stb[B_ * T_];
__device__ double g_part[B_ * 96 * 2];
__device__ float g_stats[B_ * 4];

// stage layout (u32 units): Ah@0, Al@2176, Bh@4352, Bl@6528; stage stride 8704
#define STG 8704
#define AL_OFF 2176
#define BH_OFF 4352
#define BL_OFF 6528

// ---------------- 0) pre-split kernels ----------------
__global__ void presplit_adj_kernel(const float* __restrict__ adj) {
    int idx = blockIdx.x * 256 + threadIdx.x;      // kp*1024 + n
    int kp = idx >> 10, n = idx & 1023;
    unsigned h, l;
    split2(adj[(size_t)n * N_ + 2 * kp], adj[(size_t)n * N_ + 2 * kp + 1], h, l);
    g_adjh[idx] = h; g_adjl[idx] = l;
}
__global__ void presplit_sig_kernel(const float* __restrict__ sig) {
    int idx = blockIdx.x * 256 + threadIdx.x;      // (bt*(N/2)+kp)*64 + c
    int bt = idx / ((N_ / 2) * C_);
    int r = idx % ((N_ / 2) * C_);
    int kp = r / C_, c = r % C_;
    const float* s = sig + ((size_t)bt * N_ + 2 * kp) * C_ + c;
    unsigned h, l;
    split2(s[0], s[C_], h, l);
    g_sigh[idx] = h; g_sigl[idx] = l;
}
__global__ void presplit_w_kernel(const float* __restrict__ Wq,
                                  const float* __restrict__ Wk) {
    int idx = blockIdx.x * 256 + threadIdx.x;
    int kp = idx / HD_, m = idx % HD_;
    const float* W = blockIdx.y ? Wk : Wq;
    unsigned long long* o = blockIdx.y ? g_wks : g_wqs;
    o[idx] = splitpack(W[(size_t)(2 * kp) * HD_ + m], W[(size_t)(2 * kp + 1) * HD_ + m]);
}
__global__ void presplit_state_kernel(const float* __restrict__ state) {
    int idx = blockIdx.x * 256 + threadIdx.x;
    int kp = idx / BT_, bt = idx % BT_;
    g_states[idx] = splitpack(state[(size_t)bt * N_ + 2 * kp],
                              state[(size_t)bt * N_ + 2 * kp + 1]);
}

// ---------------- 1) q/k projections (tensor) ----------------
__global__ void __launch_bounds__(256) qkT_kernel(const float* __restrict__ bq,
                                                  const float* __restrict__ bk) {
    __shared__ unsigned Ah[16][104], Al[16][104], Bh[16][72], Bl[16][72];
    int j0 = blockIdx.x * 64;
    int isk = blockIdx.y;
    const unsigned long long* W = isk ? g_wks : g_wqs;
    int tid = threadIdx.x, lane = tid & 31, wc = tid >> 5;
    int lq = lane >> 2, lr = lane & 3;

    float acc[6][4];
#pragma unroll
    for (int i = 0; i < 6; i++)
#pragma unroll
        for (int r = 0; r < 4; r++) acc[i][r] = 0.f;

    for (int kc = 0; kc < 32; kc++) {
        int kp0 = kc * 16;
#pragma unroll
        for (int p = 0; p < 6; p++) {
            int e = tid + p * 256;
            int kp = e & 15, m = e >> 4;
            unsigned long long v = g_states[(size_t)(kp0 + kp) * BT_ + m];
            Ah[kp][m] = (unsigned)v; Al[kp][m] = (unsigned)(v >> 32);
        }
#pragma unroll
        for (int p = 0; p < 4; p++) {
            int e = tid + p * 256;
            int kp = e >> 6, jf = e & 63;
            unsigned long long v = W[(size_t)(kp0 + kp) * HD_ + j0 + jf];
            Bh[kp][jf] = (unsigned)v; Bl[kp][jf] = (unsigned)(v >> 32);
        }
        __syncthreads();
#pragma unroll
        for (int ks = 0; ks < 2; ks++) {
            int kb = ks * 8;
            int col = wc * 8 + lq;
            unsigned bh0 = Bh[kb + lr][col], bh1 = Bh[kb + lr + 4][col];
            unsigned bl0 = Bl[kb + lr][col], bl1 = Bl[kb + lr + 4][col];
#pragma unroll
            for (int i = 0; i < 6; i++) {
                int m = i * 16 + lq;
                unsigned ah0 = Ah[kb + lr][m],     ah1 = Ah[kb + lr][m + 8];
                unsigned ah2 = Ah[kb + lr + 4][m], ah3 = Ah[kb + lr + 4][m + 8];
                unsigned al0 = Al[kb + lr][m],     al1 = Al[kb + lr][m + 8];
                unsigned al2 = Al[kb + lr + 4][m], al3 = Al[kb + lr + 4][m + 8];
                mma16816(acc[i], ah0, ah1, ah2, ah3, bh0, bh1);
                mma16816(acc[i], ah0, ah1, ah2, ah3, bl0, bl1);
                mma16816(acc[i], al0, al1, al2, al3, bh0, bh1);
            }
        }
        __syncthreads();
    }
    const float* bias = isk ? bk : bq;
    float* out = isk ? g_k : g_q;
    int col = j0 + wc * 8 + lr * 2;
    float b0 = bias[col], b1 = bias[col + 1];
#pragma unroll
    for (int i = 0; i < 6; i++) {
        int row = i * 16 + lq;
        *(float2*)(out + (size_t)row * HD_ + col) =
            make_float2(acc[i][0] + b0, acc[i][1] + b1);
        *(float2*)(out + (size_t)(row + 8) * HD_ + col) =
            make_float2(acc[i][2] + b0, acc[i][3] + b1);
    }
}

// ---------------- 2) attention weights ----------------
__global__ void attw_kernel() {
    __shared__ float sc[T_][T_];
    int b = blockIdx.x % B_;
    int h = blockIdx.x / B_;
    int t = threadIdx.x;
    int i = t / T_, j = t % T_;
    if (t < T_ * T_) {
        const float* qp = &g_q[(b * T_ + i) * HD_ + h * D_];
        const float* kp = &g_k[(b * T_ + j) * HD_ + h * D_];
        float d = 0.f;
#pragma unroll
        for (int x = 0; x < D_; x++) d = fmaf(qp[x], kp[x], d);
        sc[i][j] = d * 0.125f;
    }
    __syncthreads();
    if (t < T_ * T_) {
        float mx = -1e30f;
#pragma unroll
        for (int x = 0; x < T_; x++) mx = fmaxf(mx, sc[i][x]);
        float sm = 0.f;
#pragma unroll
        for (int x = 0; x < T_; x++) sm += expf(sc[i][x] - mx);
        g_w[((h * B_ + b) * T_ + i) * T_ + j] = expf(sc[i][j] - mx) / sm;
    }
}

// ---------------- 3) per-(t,h) weight folds ----------------
__global__ void kwf_kernel(const float* __restrict__ Kg, const float* __restrict__ Wf,
                           const float* __restrict__ Ws, const float* __restrict__ bg) {
    __shared__ float sKg[64][65], sWf[64][66], sWs[64], sbg[64];
    int t = blockIdx.x / H_, h = blockIdx.x % H_;
    int tid = threadIdx.x;
#pragma unroll
    for (int p = 0; p < 16; p++) {
        int e = tid + p * 256;
        int cp = e >> 6, k = e & 63;
        sKg[cp][k] = Kg[((size_t)t * C_ + cp) * HD_ + h * D_ + k];
        sWf[cp][k] = Wf[(size_t)(h * D_ + cp) * C_ + k];
    }
    if (tid < 64) {
        sWs[tid] = Ws[h * D_ + tid];
        sbg[tid] = bg[t * HD_ + h * D_ + tid];
    }
    __syncthreads();
    int cp = tid >> 2, cg = (tid & 3) * 16;
    float acc[16];
#pragma unroll
    for (int j = 0; j < 16; j++) acc[j] = 0.f;
    for (int k = 0; k < 64; k++) {
        float a = sKg[cp][k];
#pragma unroll
        for (int j = 0; j < 16; j++) acc[j] = fmaf(a, sWf[k][cg + j], acc[j]);
    }
    float* o = g_kwf + (((size_t)t * H_ + h) * C_ + cp) * C_ + cg;
#pragma unroll
    for (int j = 0; j < 16; j++) o[j] = acc[j];
    if (tid < 64) {
        float s = 0.f;
        for (int k = 0; k < 64; k++) s = fmaf(sKg[tid][k], sWs[k], s);
        g_kgws[((size_t)t * H_ + h) * C_ + tid] = s;
    } else if (tid < 128) {
        int c = tid - 64;
        float s = 0.f;
        for (int k = 0; k < 64; k++) s = fmaf(sbg[k], sWf[k][c], s);
        g_bgwf[((size_t)t * H_ + h) * C_ + c] = s;
    } else if (tid == 128) {
        float s = 0.f;
        for (int k = 0; k < 64; k++) s = fmaf(sbg[k], sWs[k], s);
        g_bgws[t * H_ + h] = s;
    }
}

// ---------------- 4) WK planes ----------------
__global__ void wk_kernel() {
    __shared__ float sw[H_];
    int blk = blockIdx.x;
    int t = blk % T_;
    int bq = blk / T_;
    int q = bq % T_, b = bq / T_;
    int tid = threadIdx.x;
    if (tid < H_) sw[tid] = g_w[((tid * B_ + b) * T_ + q) * T_ + t];
    __syncthreads();
    unsigned* outh = g_wk2h + (size_t)blk * 2048;
    unsigned* outl = g_wk2l + (size_t)blk * 2048;
#pragma unroll
    for (int p = 0; p < 8; p++) {
        int idx = tid + p * 256;
        int kp = idx >> 6, c = idx & 63;
        float v0 = 0.f, v1 = 0.f;
#pragma unroll
        for (int h = 0; h < H_; h++) {
            const float* kw = g_kwf + ((size_t)t * H_ + h) * (C_ * C_);
            v0 = fmaf(sw[h], kw[(2 * kp) * C_ + c], v0);
            v1 = fmaf(sw[h], kw[(2 * kp + 1) * C_ + c], v1);
        }
        unsigned h2, l2;
        split2(v0, v1, h2, l2);
        outh[idx] = h2; outl[idx] = l2;
    }
}

// ---------------- 5) small mixes ----------------
__global__ void mix_kernel() {
    __shared__ float sw2[H_ * T_];
    int bq = blockIdx.x;
    int q = bq % T_, b = bq / T_;
    int tid = threadIdx.x;
    if (tid < H_ * T_) {
        int h = tid / T_, t = tid % T_;
        sw2[tid] = g_w[((h * B_ + b) * T_ + q) * T_ + t];
    }
    __syncthreads();
    for (int idx = tid; idx < T_ * C_; idx += 128) {
        int t = idx >> 6, cp = idx & 63;
        float s = 0.f;
#pragma unroll
        for (int h = 0; h < H_; h++)
            s = fmaf(sw2[h * T_ + t], g_kgws[((size_t)t * H_ + h) * C_ + cp], s);
        g_kws[((size_t)bq * T_ + t) * C_ + cp] = s;
    }
    if (tid < C_) {
        float s = 0.f;
        for (int t = 0; t < T_; t++)
#pragma unroll
            for (int h = 0; h < H_; h++)
                s = fmaf(sw2[h * T_ + t], g_bgwf[((size_t)t * H_ + h) * C_ + tid], s);
        g_bgf[(size_t)bq * C_ + tid] = s;
    } else if (tid == 64) {
        float s = 0.f;
        for (int t = 0; t < T_; t++)
            for (int h = 0; h < H_; h++)
                s = fmaf(sw2[h * T_ + t], g_bgws[t * H_ + h], s);
        g_stb[bq] = s;
    }
}

// ---------------- 6) agg = adj @ sig_cat (3-stage, 4 warps x 64x64) ----------------
__global__ void __launch_bounds__(128, 2) aggT_kernel() {
    extern __shared__ unsigned sm[];
    unsigned sbase = smem_u32addr(sm);
    int j0 = blockIdx.x * 128;
    int n0 = blockIdx.y * 128;
    int tid = threadIdx.x, lane = tid & 31, wid = tid >> 5;
    int wm = (wid & 1) * 64, wn = (wid >> 1) * 64;
    int lq = lane >> 2, lr = lane & 3;

    auto load_stage = [&](int stage, int kc) {
        int kp0 = kc * 16;
        unsigned so = sbase + stage * (STG * 4);
#pragma unroll
        for (int p = 0; p < 4; p++) {
            int e = tid + p * 128;
            int kp = e >> 5, mc = (e & 31) * 4;
            size_t ga = (size_t)(kp0 + kp) * N_;
            cpasync16(so + (kp * 136 + mc) * 4, g_adjh + ga + n0 + mc);
            cpasync16(so + (AL_OFF + kp * 136 + mc) * 4, g_adjl + ga + n0 + mc);
            int j = j0 + mc, bt = j >> 6, c = j & 63;
            size_t gb = ((size_t)bt * (N_ / 2) + kp0 + kp) * C_ + c;
            cpasync16(so + (BH_OFF + kp * 136 + mc) * 4, g_sigh + gb);
            cpasync16(so + (BL_OFF + kp * 136 + mc) * 4, g_sigl + gb);
        }
        CP_COMMIT();
    };

    float acc[4][8][4];
#pragma unroll
    for (int i = 0; i < 4; i++)
#pragma unroll
        for (int j = 0; j < 8; j++)
#pragma unroll
            for (int r = 0; r < 4; r++) acc[i][j][r] = 0.f;

    load_stage(0, 0);
    load_stage(1, 1);
    int cur = 0;
    for (int kc = 0; kc < 32; kc++) {
        if (kc + 2 < 32) { load_stage((cur + 2) % 3, kc + 2); CP_WAIT2(); }
        else if (kc + 1 < 32) CP_WAIT1();
        else CP_WAIT0();
        __syncthreads();
        const unsigned* Ah = sm + cur * STG;
        const unsigned* Al = Ah + AL_OFF;
        const unsigned* Bh = Ah + BH_OFF;
        const unsigned* Bl = Ah + BL_OFF;
#pragma unroll
        for (int ks = 0; ks < 2; ks++) {
            int kb = ks * 8;
            unsigned bh[8][2], bl[8][2];
#pragma unroll
            for (int j = 0; j < 8; j++) {
                int col = wn + j * 8 + lq;
                bh[j][0] = Bh[(kb + lr) * 136 + col];     bh[j][1] = Bh[(kb + lr + 4) * 136 + col];
                bl[j][0] = Bl[(kb + lr) * 136 + col];     bl[j][1] = Bl[(kb + lr + 4) * 136 + col];
            }
#pragma unroll
            for (int i = 0; i < 4; i++) {
                int m = wm + i * 16 + lq;
                unsigned ah0 = Ah[(kb + lr) * 136 + m],     ah1 = Ah[(kb + lr) * 136 + m + 8];
                unsigned ah2 = Ah[(kb + lr + 4) * 136 + m], ah3 = Ah[(kb + lr + 4) * 136 + m + 8];
                unsigned al0 = Al[(kb + lr) * 136 + m],     al1 = Al[(kb + lr) * 136 + m + 8];
                unsigned al2 = Al[(kb + lr + 4) * 136 + m], al3 = Al[(kb + lr + 4) * 136 + m + 8];
#pragma unroll
                for (int j = 0; j < 8; j++) {
                    mma16816(acc[i][j], ah0, ah1, ah2, ah3, bh[j][0], bh[j][1]);
                    mma16816(acc[i][j], ah0, ah1, ah2, ah3, bl[j][0], bl[j][1]);
                    mma16816(acc[i][j], al0, al1, al2, al3, bh[j][0], bh[j][1]);
                }
            }
        }
        __syncthreads();
        cur = (cur + 1) % 3;
    }
    // epilogue: write agg planes, k-major [bt][kp][n]
#pragma unroll
    for (int i = 0; i < 4; i++) {
        int row = n0 + wm + i * 16 + lq;
#pragma unroll
        for (int j = 0; j < 8; j++) {
            int jcol = j0 + wn + j * 8 + lr * 2;
            int bt = jcol >> 6, c2 = (jcol & 63) >> 1;
            size_t o = ((size_t)bt * 32 + c2) * N_;
            unsigned h, l;
            split2(acc[i][j][0], acc[i][j][1], h, l);
            g_aggh[o + row] = h; g_aggl[o + row] = l;
            split2(acc[i][j][2], acc[i][j][3], h, l);
            g_aggh[o + row + 8] = h; g_aggl[o + row + 8] = l;
        }
    }
}

// ---------------- 7) fused signal GEMM (3-stage, 4 warps x 64x64) ----------
__global__ void __launch_bounds__(128, 2) fusedsig2_kernel(
    const float* __restrict__ bf, const float* __restrict__ sig,
    float* __restrict__ out_sig) {
    extern __shared__ unsigned sm[];
    unsigned sbase = smem_u32addr(sm);
    int j0 = blockIdx.x * 128;
    int n0 = blockIdx.y * 128;
    int b = blockIdx.z;
    int tid = threadIdx.x, lane = tid & 31, wid = tid >> 5;
    int wm = (wid & 1) * 64, wn = (wid >> 1) * 64;
    int lq = lane >> 2, lr = lane & 3;

    auto load_stage = [&](int stage, int kc) {
        int kpg0 = kc * 16;
        int t = kpg0 >> 5;
        int kpl0 = kpg0 & 31;
        unsigned so = sbase + stage * (STG * 4);
#pragma unroll
        for (int p = 0; p < 4; p++) {
            int e = tid + p * 128;
            int kp = e >> 5, mc = (e & 31) * 4;
            size_t ga = ((size_t)(b * T_ + t) * 32 + kpl0 + kp) * N_ + n0 + mc;
            cpasync16(so + (kp * 136 + mc) * 4, g_aggh + ga);
            cpasync16(so + (AL_OFF + kp * 136 + mc) * 4, g_aggl + ga);
            int j = j0 + mc, q = j >> 6, c = j & 63;
            size_t gb = (((size_t)(b * T_ + q) * T_ + t) << 11) + (kpl0 + kp) * 64 + c;
            cpasync16(so + (BH_OFF + kp * 136 + mc) * 4, g_wk2h + gb);
            cpasync16(so + (BL_OFF + kp * 136 + mc) * 4, g_wk2l + gb);
        }
        CP_COMMIT();
    };

    float acc[4][8][4];
#pragma unroll
    for (int i = 0; i < 4; i++)
#pragma unroll
        for (int j = 0; j < 8; j++)
#pragma unroll
            for (int r = 0; r < 4; r++) acc[i][j][r] = 0.f;

    load_stage(0, 0);
    load_stage(1, 1);
    int cur = 0;
    for (int kc = 0; kc < 24; kc++) {
        if (kc + 2 < 24) { load_stage((cur + 2) % 3, kc + 2); CP_WAIT2(); }
        else if (kc + 1 < 24) CP_WAIT1();
        else CP_WAIT0();
        __syncthreads();
        const unsigned* Ah = sm + cur * STG;
        const unsigned* Al = Ah + AL_OFF;
        const unsigned* Bh = Ah + BH_OFF;
        const unsigned* Bl = Ah + BL_OFF;
#pragma unroll
        for (int ks = 0; ks < 2; ks++) {
            int kb = ks * 8;
            unsigned bh[8][2], bl[8][2];
#pragma unroll
            for (int j = 0; j < 8; j++) {
                int col = wn + j * 8 + lq;
                bh[j][0] = Bh[(kb + lr) * 136 + col];     bh[j][1] = Bh[(kb + lr + 4) * 136 + col];
                bl[j][0] = Bl[(kb + lr) * 136 + col];     bl[j][1] = Bl[(kb + lr + 4) * 136 + col];
            }
#pragma unroll
            for (int i = 0; i < 4; i++) {
                int m = wm + i * 16 + lq;
                unsigned ah0 = Ah[(kb + lr) * 136 + m],     ah1 = Ah[(kb + lr) * 136 + m + 8];
                unsigned ah2 = Ah[(kb + lr + 4) * 136 + m], ah3 = Ah[(kb + lr + 4) * 136 + m + 8];
                unsigned al0 = Al[(kb + lr) * 136 + m],     al1 = Al[(kb + lr) * 136 + m + 8];
                unsigned al2 = Al[(kb + lr + 4) * 136 + m], al3 = Al[(kb + lr + 4) * 136 + m + 8];
#pragma unroll
                for (int j = 0; j < 8; j++) {
                    mma16816(acc[i][j], ah0, ah1, ah2, ah3, bh[j][0], bh[j][1]);
                    mma16816(acc[i][j], ah0, ah1, ah2, ah3, bl[j][0], bl[j][1]);
                    mma16816(acc[i][j], al0, al1, al2, al3, bh[j][0], bh[j][1]);
                }
            }
        }
        __syncthreads();
        cur = (cur + 1) % 3;
    }
#pragma unroll
    for (int i = 0; i < 4; i++) {
        int row = n0 + wm + i * 16 + lq;
#pragma unroll
        for (int j = 0; j < 8; j++) {
            int jcol = j0 + wn + j * 8 + lr * 2;
            int q = jcol >> 6, c = jcol & 63;
            float2 bgf2 = *(const float2*)(g_bgf + (size_t)(b * T_ + q) * C_ + c);
            float2 bf2 = *(const float2*)(bf + c);
            float bb0 = bgf2.x + bf2.x, bb1 = bgf2.y + bf2.y;
            size_t o0 = ((size_t)(b * T_ + q) * N_ + row) * C_ + c;
            size_t o1 = ((size_t)(b * T_ + q) * N_ + row + 8) * C_ + c;
            float2 sg0 = *(const float2*)(sig + o0);
            float2 sg1 = *(const float2*)(sig + o1);
            *(float2*)(out_sig + o0) =
                make_float2(fmaxf(acc[i][j][0] + bb0, 0.f) + sg0.x,
                            fmaxf(acc[i][j][1] + bb1, 0.f) + sg0.y);
            *(float2*)(out_sig + o1) =
                make_float2(fmaxf(acc[i][j][2] + bb0, 0.f) + sg1.x,
                            fmaxf(acc[i][j][3] + bb1, 0.f) + sg1.y);
        }
    }
}

// ---------------- 8) fused state ----------------
__global__ void fusedstate_kernel(const float* __restrict__ state,
                                  const float* __restrict__ bs,
                                  float* __restrict__ out_state) {
    __shared__ float sagg[128][67];
    __shared__ float skt[T_][C_];
    __shared__ float sstb[T_];
    int n0 = blockIdx.x * 128;
    int b = blockIdx.y;
    int tid = threadIdx.x;
    if (tid < T_) sstb[tid] = g_stb[b * T_ + tid];
    float st[T_];
#pragma unroll
    for (int q = 0; q < T_; q++) st[q] = 0.f;

    for (int t = 0; t < T_; t++) {
        __syncthreads();
#pragma unroll
        for (int p = 0; p < 32; p++) {
            int idx = tid + p * 128;
            int kp = idx >> 7, n = idx & 127;
            size_t g = ((size_t)(b * T_ + t) * 32 + kp) * N_ + n0 + n;
            unsigned h = g_aggh[g], l = g_aggl[g];
            sagg[n][2 * kp] = comb_lo(h, l);
            sagg[n][2 * kp + 1] = comb_hi(h, l);
        }
#pragma unroll
        for (int p = 0; p < 6; p++) {
            int idx = tid + p * 128;
            int q = idx >> 6, cp = idx & 63;
            skt[q][cp] = g_kws[((size_t)(b * T_ + q) * T_ + t) * C_ + cp];
        }
        __syncthreads();
#pragma unroll 8
        for (int c = 0; c < C_; c++) {
            float a = sagg[tid][c];
#pragma unroll
            for (int q = 0; q < T_; q++) st[q] = fmaf(a, skt[q][c], st[q]);
        }
    }
    __syncthreads();
#pragma unroll
    for (int q = 0; q < T_; q++) {
        size_t idx = (size_t)(b * T_ + q) * N_ + n0 + tid;
        out_state[idx] = state[idx] + fmaxf(st[q] + sstb[q] + bs[0], 0.f);
    }
}

// ---------------- LayerNorm statistics ----------------
__global__ void red_state_kernel(const float* __restrict__ ys) {
    __shared__ double ss[256], sq[256];
    int b = blockIdx.x;
    int tid = threadIdx.x;
    double s = 0, q = 0;
    for (int i = tid; i < T_ * N_; i += 256) {
        double x = ys[b * T_ * N_ + i];
        s += x; q += x * x;
    }
    ss[tid] = s; sq[tid] = q;
    __syncthreads();
    for (int o = 128; o; o >>= 1) {
        if (tid < o) { ss[tid] += ss[tid + o]; sq[tid] += sq[tid + o]; }
        __syncthreads();
    }
    if (tid == 0) {
        double cnt = (double)(T_ * N_);
        double mean = ss[0] / cnt;
        double var = sq[0] / cnt - mean * mean;
        g_stats[b * 4 + 0] = (float)mean;
        g_stats[b * 4 + 1] = rsqrtf((float)var + EPSV);
    }
}

__global__ void red_sig1_kernel(const float* __restrict__ yg) {
    __shared__ double ss[256], sq[256];
    int b = blockIdx.y, blk = blockIdx.x;
    int tid = threadIdx.x;
    const float* base = yg + (size_t)b * (T_ * N_ * C_) + blk * 8192;
    double s = 0, q = 0;
    for (int i = tid; i < 8192; i += 256) {
        double x = base[i];
        s += x; q += x * x;
    }
    ss[tid] = s; sq[tid] = q;
    __syncthreads();
    for (int o = 128; o; o >>= 1) {
        if (tid < o) { ss[tid] += ss[tid + o]; sq[tid] += sq[tid + o]; }
        __syncthreads();
    }
    if (tid == 0) {
        g_part[(b * 96 + blk) * 2 + 0] = ss[0];
        g_part[(b * 96 + blk) * 2 + 1] = sq[0];
    }
}

__global__ void red_sig2_kernel() {
    __shared__ double ss[128], sq[128];
    int b = blockIdx.x;
    int tid = threadIdx.x;
    double s = 0, q = 0;
    if (tid < 96) {
        s = g_part[(b * 96 + tid) * 2 + 0];
        q = g_part[(b * 96 + tid) * 2 + 1];
    }
    ss[tid] = s; sq[tid] = q;
    __syncthreads();
    for (int o = 64; o; o >>= 1) {
        if (tid < o) { ss[tid] += ss[tid + o]; sq[tid] += sq[tid + o]; }
        __syncthreads();
    }
    if (tid == 0) {
        double cnt = (double)T_ * N_ * C_;
        double mean = ss[0] / cnt;
        double var = sq[0] / cnt - mean * mean;
        g_stats[b * 4 + 2] = (float)mean;
        g_stats[b * 4 + 3] = rsqrtf((float)var + EPSV);
    }
}

// ---------------- in-place normalization ----------------
__global__ void norm_state_kernel(float* __restrict__ ys,
                                  const float* __restrict__ gamma,
                                  const float* __restrict__ beta) {
    int idx = blockIdx.x * 256 + threadIdx.x;
    int b = idx / (T_ * N_);
    int r = idx % (T_ * N_);
    ys[idx] = (ys[idx] - g_stats[b * 4 + 0]) * g_stats[b * 4 + 1] * gamma[r] + beta[r];
}

__global__ void norm_sig_kernel(float* __restrict__ yg,
                                const float* __restrict__ gamma,
                                const float* __restrict__ beta) {
    int idx = blockIdx.x * 256 + threadIdx.x;
    int b = idx / (T_ * N_ * C_);
    int r = idx % (T_ * N_ * C_);
    yg[idx] = (yg[idx] - g_stats[b * 4 + 2]) * g_stats[b * 4 + 3] * gamma[r] + beta[r];
}

// ---------------- launch ----------------
extern "C" void kernel_launch(void* const* d_in, const int* in_sizes, int n_in,
                              void* d_out, int out_size) {
    const float* graph_state  = (const float*)d_in[0];
    const float* graph_signal = (const float*)d_in[1];
    const float* adj          = (const float*)d_in[2];
    const float* Wq           = (const float*)d_in[3];
    const float* bq           = (const float*)d_in[4];
    const float* Wk           = (const float*)d_in[5];
    const float* bk           = (const float*)d_in[6];
    const float* Kg           = (const float*)d_in[7];
    const float* bg           = (const float*)d_in[8];
    const float* Ws           = (const float*)d_in[9];
    const float* bs           = (const float*)d_in[10];
    const float* Wf           = (const float*)d_in[11];
    const float* bf           = (const float*)d_in[12];
    const float* gs_gamma     = (const float*)d_in[13];
    const float* gs_beta      = (const float*)d_in[14];
    const float* sg_gamma     = (const float*)d_in[15];
    const float* sg_beta      = (const float*)d_in[16];

    float* out_state  = (float*)d_out;
    float* out_signal = out_state + BT_ * N_;

    const int pipe_smem = 3 * STG * 4;   // 104448 bytes
    cudaFuncSetAttribute(aggT_kernel,
                         cudaFuncAttributeMaxDynamicSharedMemorySize, pipe_smem);
    cudaFuncSetAttribute(fusedsig2_kernel,
                         cudaFuncAttributeMaxDynamicSharedMemorySize, pipe_smem);

    presplit_adj_kernel<<<(N_ * N_ / 2) / 256, 256>>>(adj);
    presplit_sig_kernel<<<(BT_ * (N_ / 2) * C_) / 256, 256>>>(graph_signal);
    presplit_w_kernel<<<dim3(((N_ / 2) * HD_) / 256, 2), 256>>>(Wq, Wk);
    presplit_state_kernel<<<((N_ / 2) * BT_) / 256, 256>>>(graph_state);
    qkT_kernel<<<dim3(8, 2), 256>>>(bq, bk);
    attw_kernel<<<H_ * B_, 160>>>();
    kwf_kernel<<<T_ * H_, 256>>>(Kg, Wf, Ws, bg);
    wk_kernel<<<B_ * T_ * T_, 256>>>();
    mix_kernel<<<B_ * T_, 128>>>();
    aggT_kernel<<<dim3(48, 8), 128, pipe_smem>>>();
    fusedsig2_kernel<<<dim3(6, 8, B_), 128, pipe_smem>>>(bf, graph_signal, out_signal);
    fusedstate_kernel<<<dim3(8, 8), 128>>>(graph_state, bs, out_state);
    red_state_kernel<<<B_, 256>>>(out_state);
    red_sig1_kernel<<<dim3(96, B_), 256>>>(out_signal);
    red_sig2_kernel<<<B_, 128>>>();
    norm_state_kernel<<<(BT_ * N_) / 256, 256>>>(out_state, gs_gamma, gs_beta);
    norm_sig_kernel<<<(BT_ * N_ * C_) / 256, 256>>>(out_signal, sg_gamma, sg_beta);
}